// round 9
// baseline (speedup 1.0000x reference)
#include <cuda_runtime.h>
#include <math.h>

#define HN 8
#define LN 512
#define FQ 416
#define FV 448
#define NPROJ 3456
#define NFEAT 2304

// ---------------- scratch (static __device__, no allocation) ----------------
__device__ float g_Win[512*NPROJ];
__device__ float g_bvec[NPROJ];
__device__ float g_Wout[NFEAT*512];
__device__ float g_proj[LN*NPROJ];
__device__ float g_cosb[LN*96];
__device__ float g_sinb[LN*96];
__device__ float g_Qf[HN*LN*FQ];
__device__ float g_Kf[HN*LN*FQ];
__device__ float g_Vf[HN*LN*FV];
__device__ float g_attn[HN*LN*LN];
__device__ float g_OV[HN*LN*FV];
__device__ float g_feat[LN*NFEAT];
__device__ float g_part[4*LN*512];

// ---------------- helpers ----------------
__device__ __forceinline__ float tf32f(float x) {
    unsigned u;
    asm("cvt.rna.tf32.f32 %0, %1;" : "=r"(u) : "f"(x));
    return __uint_as_float(u);
}

__device__ __forceinline__ void mma_tf32(float4& d, const unsigned* a,
                                         unsigned b0, unsigned b1) {
    asm volatile(
        "mma.sync.aligned.m16n8k8.row.col.f32.tf32.tf32.f32 "
        "{%0,%1,%2,%3},{%4,%5,%6,%7},{%8,%9},{%0,%1,%2,%3};"
        : "+f"(d.x), "+f"(d.y), "+f"(d.z), "+f"(d.w)
        : "r"(a[0]), "r"(a[1]), "r"(a[2]), "r"(a[3]), "r"(b0), "r"(b1));
}

// ------------- split-TF32 tensor-core GEMM: 128x64 tile --------------------
// C[M,N] = [C +] A[M,K] @ (TRANSB ? B[N,K]^T : B[K,N]) [+ bias].
// A pre-split (hi/lo smem tiles at staging); B raw fp32 in smem.
// NTERMS=3: acc += al*bh + ah*bl + ah*bh   (~fp32 accuracy)
// NTERMS=2: acc += al*bh + ah*bh           (B low bits dropped, ~tf32-eps rel)
// Smem: 2*2*16*136*4 + 2*16*72*4 = 44032 B (< 48KB static limit).
// M%128==0, N%64==0, K%16==0. All pointers float4-aligned.
template<int TRANSB, int NTERMS>
__global__ void __launch_bounds__(256)
gemm3x(const float* __restrict__ A, int lda, long long sA,
       const float* __restrict__ B, int ldb, long long sB,
       float* __restrict__ C, int ldc, long long sC,
       int K, int accum, const float* __restrict__ bias)
{
    __shared__ float Ah[2][16][136];  // [k][m] hi, stride%32==8 -> conflict-free
    __shared__ float Al[2][16][136];  // [k][m] lo
    __shared__ float Bs[2][16][72];   // [k][n] raw fp32
    const int bz = blockIdx.z;
    A += (long long)bz * sA;
    B += (long long)bz * sB;
    C += (long long)bz * sC;
    const int row0 = blockIdx.y * 128, col0 = blockIdx.x * 64;
    const int tid = threadIdx.x;
    const int lane = tid & 31, wid = tid >> 5;
    const int g = lane >> 2, tig = lane & 3;
    const int wm = (wid & 3) * 32, wn = (wid >> 2) * 32;

    const int am = tid >> 2, akq = tid & 3;
    const float* pA0 = A + (long long)(row0 + am) * lda + akq * 4;
    const float* pA1 = A + (long long)(row0 + am + 64) * lda + akq * 4;
    const float* pB;
    int bn = 0, bkq = 0, bkk = 0, bnq = 0;
    if (TRANSB) {
        bn = tid >> 2; bkq = tid & 3;
        pB = B + (long long)(col0 + bn) * ldb + bkq * 4;
    } else {
        bkk = tid >> 4; bnq = tid & 15;
        pB = B + (long long)bkk * ldb + col0 + bnq * 4;
    }

    float4 acc[2][4];
#pragma unroll
    for (int mf = 0; mf < 2; mf++)
#pragma unroll
        for (int nf = 0; nf < 4; nf++) acc[mf][nf] = make_float4(0.f,0.f,0.f,0.f);

    float4 ra0 = *(const float4*)pA0;
    float4 ra1 = *(const float4*)pA1;
    float4 rb  = *(const float4*)pB;

#define SPLIT_STORE_A(bf, kk, mm, v)                                       \
    do { float _h = tf32f(v); Ah[bf][kk][mm] = _h;                         \
         Al[bf][kk][mm] = tf32f((v) - _h); } while (0)

#define STORE_TILE(bf)                                                     \
    do {                                                                   \
        SPLIT_STORE_A(bf, akq*4+0, am,    ra0.x);                          \
        SPLIT_STORE_A(bf, akq*4+1, am,    ra0.y);                          \
        SPLIT_STORE_A(bf, akq*4+2, am,    ra0.z);                          \
        SPLIT_STORE_A(bf, akq*4+3, am,    ra0.w);                          \
        SPLIT_STORE_A(bf, akq*4+0, am+64, ra1.x);                          \
        SPLIT_STORE_A(bf, akq*4+1, am+64, ra1.y);                          \
        SPLIT_STORE_A(bf, akq*4+2, am+64, ra1.z);                          \
        SPLIT_STORE_A(bf, akq*4+3, am+64, ra1.w);                          \
        if (TRANSB) {                                                      \
            Bs[bf][bkq*4+0][bn] = rb.x;                                    \
            Bs[bf][bkq*4+1][bn] = rb.y;                                    \
            Bs[bf][bkq*4+2][bn] = rb.z;                                    \
            Bs[bf][bkq*4+3][bn] = rb.w;                                    \
        } else {                                                           \
            *(float4*)&Bs[bf][bkk][bnq*4] = rb;                            \
        }                                                                  \
    } while (0)

#define COMPUTE_TILE(bf)                                                   \
    do {                                                                   \
        _Pragma("unroll")                                                  \
        for (int ks = 0; ks < 2; ks++) {                                   \
            const int k0 = ks * 8;                                         \
            unsigned ah[2][4], al[2][4], bh[4][2], bl[4][2];               \
            _Pragma("unroll")                                              \
            for (int mf = 0; mf < 2; mf++) {                               \
                int m0 = wm + mf * 16;                                     \
                ah[mf][0] = __float_as_uint(Ah[bf][k0+tig  ][m0+g  ]);     \
                ah[mf][1] = __float_as_uint(Ah[bf][k0+tig  ][m0+g+8]);     \
                ah[mf][2] = __float_as_uint(Ah[bf][k0+tig+4][m0+g  ]);     \
                ah[mf][3] = __float_as_uint(Ah[bf][k0+tig+4][m0+g+8]);     \
                al[mf][0] = __float_as_uint(Al[bf][k0+tig  ][m0+g  ]);     \
                al[mf][1] = __float_as_uint(Al[bf][k0+tig  ][m0+g+8]);     \
                al[mf][2] = __float_as_uint(Al[bf][k0+tig+4][m0+g  ]);     \
                al[mf][3] = __float_as_uint(Al[bf][k0+tig+4][m0+g+8]);     \
            }                                                              \
            _Pragma("unroll")                                              \
            for (int nf = 0; nf < 4; nf++) {                               \
                int n0 = wn + nf * 8;                                      \
                float w0 = Bs[bf][k0+tig  ][n0+g];                         \
                float w1 = Bs[bf][k0+tig+4][n0+g];                         \
                float h0 = tf32f(w0), h1 = tf32f(w1);                      \
                bh[nf][0] = __float_as_uint(h0);                           \
                bh[nf][1] = __float_as_uint(h1);                           \
                if (NTERMS == 3) {                                         \
                    bl[nf][0] = __float_as_uint(tf32f(w0 - h0));           \
                    bl[nf][1] = __float_as_uint(tf32f(w1 - h1));           \
                } else {                                                   \
                    bl[nf][0] = 0; bl[nf][1] = 0;                          \
                }                                                          \
            }                                                              \
            _Pragma("unroll")                                              \
            for (int mf = 0; mf < 2; mf++)                                 \
                _Pragma("unroll")                                          \
                for (int nf = 0; nf < 4; nf++) {                           \
                    mma_tf32(acc[mf][nf], al[mf], bh[nf][0], bh[nf][1]);   \
                    if (NTERMS == 3)                                       \
                        mma_tf32(acc[mf][nf], ah[mf], bl[nf][0], bl[nf][1]); \
                    mma_tf32(acc[mf][nf], ah[mf], bh[nf][0], bh[nf][1]);   \
                }                                                          \
        }                                                                  \
    } while (0)

    STORE_TILE(0);
    __syncthreads();

    const int T = K >> 4;
    int buf = 0;
#pragma unroll 1
    for (int t = 1; t < T; t++) {
        pA0 += 16; pA1 += 16;
        ra0 = *(const float4*)pA0;
        ra1 = *(const float4*)pA1;
        pB += TRANSB ? 16 : (long long)16 * ldb;
        rb = *(const float4*)pB;

        COMPUTE_TILE(buf);
        int nb = buf ^ 1;
        STORE_TILE(nb);
        __syncthreads();
        buf = nb;
    }
    COMPUTE_TILE(buf);

    // epilogue: (x,y) -> (row, col..col+1); (z,w) -> (row+8, col..col+1)
#pragma unroll
    for (int mf = 0; mf < 2; mf++) {
#pragma unroll
        for (int nf = 0; nf < 4; nf++) {
            int row = row0 + wm + mf*16 + g;
            int col = col0 + wn + nf*8 + tig*2;
            long long i1 = (long long)row * ldc + col;
            long long i2 = (long long)(row + 8) * ldc + col;
            float4 v = acc[mf][nf];
            if (bias) {
                float b0 = bias[col], b1 = bias[col+1];
                v.x += b0; v.y += b1; v.z += b0; v.w += b1;
            }
            if (accum) {
                float2 o1 = *(float2*)(C + i1);
                float2 o2 = *(float2*)(C + i2);
                v.x += o1.x; v.y += o1.y; v.z += o2.x; v.w += o2.y;
            }
            *(float2*)(C + i1) = make_float2(v.x, v.y);
            *(float2*)(C + i2) = make_float2(v.z, v.w);
        }
    }
#undef STORE_TILE
#undef COMPUTE_TILE
#undef SPLIT_STORE_A
}

// ---------------- weight packing ----------------
__global__ void pack_win(const float* __restrict__ wq, const float* __restrict__ wk,
                         const float* __restrict__ wv, const float* __restrict__ wrq,
                         const float* __restrict__ wqp, const float* __restrict__ wkp,
                         const float* __restrict__ bqp, const float* __restrict__ bkp)
{
    int idx = blockIdx.x * 256 + threadIdx.x;
    if (idx < NPROJ) {
        float bv = 0.f;
        if (idx >= 3168) bv = bkp[idx - 3168];
        else if (idx >= 3072) bv = bqp[idx - 3072];
        g_bvec[idx] = bv;
    }
    if (idx >= 512 * NPROJ) return;
    int k = idx / NPROJ, c = idx % NPROJ;
    float v;
    if (c < 512)       v = wq[k*512 + c];
    else if (c < 1024) v = wk[k*512 + c - 512];
    else if (c < 1536) v = wv[k*512 + c - 1024];
    else if (c < 3072) v = wrq[k*1536 + c - 1536];
    else if (c < 3168) v = wqp[k*96 + c - 3072];
    else               v = wkp[k*288 + c - 3168];
    g_Win[idx] = v;
}

// ---------------- feature construction ----------------
// Qf/Kf layout: [0:192) rope | [192:384) remb cos/sin | [384:396) points
//               | 396 qsq/one | 397 one/ksq | [398:416) zero pad
__global__ void build_features_kernel(const float* __restrict__ trans,
                                      const float* __restrict__ head_w)
{
    int i = blockIdx.x;
    int tid = threadIdx.x;
    __shared__ float s_cos[96], s_sin[96], s_tr[3], s_hw[HN];
    if (tid < 3) s_tr[tid] = trans[i*3 + tid];
    if (tid >= 32 && tid < 32 + HN)
        s_hw[tid-32] = log1pf(expf(head_w[tid-32])) * 0.23570226039551584f;
    __syncthreads();
    if (tid < 96) {
        int c = tid / 32, k = tid % 32;
        float freq = 6.283185307179586f * expf(-(float)k * (logf(100.0f) / 31.0f));
        float sv, cv;
        sincosf(s_tr[c] * freq, &sv, &cv);
        s_cos[tid] = cv; s_sin[tid] = sv;
        g_cosb[i*96 + tid] = cv; g_sinb[i*96 + tid] = sv;
    }
    __syncthreads();

    const float* pr = g_proj + (long long)i * NPROJ;

    for (int idx = tid; idx < HN*192; idx += blockDim.x) {
        int h = idx / 192, d = idx % 192;
        int c = d / 64, f = d % 64;
        int kb = c*32 + (f & 31);
        float cs = s_cos[kb], sn = s_sin[kb];
        int col  = h*64 + f;
        int colp = h*64 + ((f < 32) ? (f + 32) : (f - 32));
        float sgn = (f < 32) ? -1.f : 1.f;
        float qv = pr[col],        q2 = pr[colp];
        float kv = pr[512 + col],  k2 = pr[512 + colp];
        float vv = pr[1024 + col], v2 = pr[1024 + colp];
        long long qo = ((long long)h*LN + i)*FQ + d;
        long long vo = ((long long)h*LN + i)*FV + d;
        g_Qf[qo] = (qv*cs + sgn*q2*sn) * 0.125f;
        g_Kf[qo] = kv*cs + sgn*k2*sn;
        g_Vf[vo] = vv*cs + sgn*v2*sn;
    }
    for (int idx = tid; idx < HN*12; idx += blockDim.x) {
        int h = idx / 12, t = idx % 12;
        int p = t / 3, c = t % 3;
        float qp = pr[3072 + c*32 + h*4  + p] + s_tr[c];
        float kp = pr[3168 + c*96 + h*12 + p] + s_tr[c];
        long long o = ((long long)h*LN + i)*FQ + 384 + t;
        g_Qf[o] = s_hw[h] * qp;
        g_Kf[o] = kp;
    }
    for (int idx = tid; idx < HN*24; idx += blockDim.x) {
        int h = idx / 24, t = idx % 24;
        int p = t / 3, c = t % 3;
        g_Vf[((long long)h*LN + i)*FV + 192 + t] =
            pr[3168 + c*96 + h*12 + 4 + p] + s_tr[c];
    }
    for (int idx = tid; idx < HN*96; idx += blockDim.x) {
        int h = idx / 96, ck = idx % 96;
        int c = ck / 32, k = ck % 32;
        float rqc = pr[1536 + h*192 + c*64 + k];
        float rqs = pr[1536 + h*192 + c*64 + 32 + k];
        float ci = s_cos[ck], si = s_sin[ck];
        const float inv = 0.07216878364870322f; // 1/sqrt(192)
        long long qo = ((long long)h*LN + i)*FQ;
        g_Qf[qo + 192 + ck] = (rqc*ci - rqs*si) * inv;
        g_Qf[qo + 288 + ck] = (rqc*si + rqs*ci) * inv;
        g_Kf[qo + 192 + ck] = ci;
        g_Kf[qo + 288 + ck] = si;
        long long vo = ((long long)h*LN + i)*FV;
        g_Vf[vo + 216 + ck] = ci;
        g_Vf[vo + 312 + ck] = si;
    }
    for (int h = tid; h < HN; h += blockDim.x) {
        float qsq = 0.f, ksq = 0.f;
        for (int p = 0; p < 4; p++)
            for (int c = 0; c < 3; c++) {
                float qv = pr[3072 + c*32 + h*4  + p] + s_tr[c];
                float kv = pr[3168 + c*96 + h*12 + p] + s_tr[c];
                qsq += qv*qv; ksq += kv*kv;
            }
        long long qo = ((long long)h*LN + i)*FQ;
        g_Qf[qo + 396] = -0.5f * s_hw[h] * qsq;
        g_Qf[qo + 397] = -0.5f * s_hw[h];
        g_Kf[qo + 396] = 1.f;
        g_Kf[qo + 397] = ksq;
        for (int t2 = 398; t2 < FQ; t2++) { g_Qf[qo + t2] = 0.f; g_Kf[qo + t2] = 0.f; }
        long long vo = ((long long)h*LN + i)*FV;
        for (int t2 = 408; t2 < FV; t2++) g_Vf[vo + t2] = 0.f;
    }
}

// ---------------- z pair-bias: shuffle-free, smem-tiled --------------------
__global__ void __launch_bounds__(256)
zbias_kernel(const float* __restrict__ z, const float* __restrict__ w_b)
{
    __shared__ float zs[256*36];
    __shared__ float wT[8*128];
    const int tid = threadIdx.x;
    const long long P0 = (long long)blockIdx.x * 256;

    for (int e = tid; e < 1024; e += 256) {
        int h = e >> 7, c = e & 127;
        wT[e] = w_b[c*8 + h];
    }

    float acc[8] = {0.f,0.f,0.f,0.f,0.f,0.f,0.f,0.f};

#pragma unroll
    for (int chunk = 0; chunk < 4; chunk++) {
        const int c0 = chunk * 32;
        __syncthreads();
#pragma unroll
        for (int k = 0; k < 8; k++) {
            int e = k*256 + tid;
            int pp = e >> 3, cq = e & 7;
            float4 v = *(const float4*)(z + (P0 + pp)*128 + c0 + cq*4);
            *(float4*)&zs[pp*36 + cq*4] = v;
        }
        __syncthreads();
#pragma unroll
        for (int s = 0; s < 8; s++) {
            float4 zv = *(const float4*)&zs[tid*36 + s*4];
            int c = c0 + s*4;
#pragma unroll
            for (int h = 0; h < 8; h++) {
                float4 wv = *(const float4*)&wT[h*128 + c];
                acc[h] += zv.x*wv.x + zv.y*wv.y + zv.z*wv.z + zv.w*wv.w;
            }
        }
    }

    const int i = (int)((P0 + tid) >> 9);
    const int j = (int)((P0 + tid) & 511);
#pragma unroll
    for (int h = 0; h < 8; h++)
        g_attn[((long long)h*LN + i)*LN + j] = acc[h];
}

// ---------------- softmax over j ----------------
__global__ void softmax_kernel()
{
    int r = blockIdx.x;
    int tid = threadIdx.x; // 128
    float4* row = (float4*)(g_attn + (long long)r * LN);
    float4 v = row[tid];
    __shared__ float red[128];
    float m = fmaxf(fmaxf(v.x, v.y), fmaxf(v.z, v.w));
    red[tid] = m; __syncthreads();
    for (int s = 64; s > 0; s >>= 1) {
        if (tid < s) red[tid] = fmaxf(red[tid], red[tid+s]);
        __syncthreads();
    }
    float M = red[0]; __syncthreads();
    float e0 = expf(v.x - M), e1 = expf(v.y - M);
    float e2 = expf(v.z - M), e3 = expf(v.w - M);
    red[tid] = e0 + e1 + e2 + e3; __syncthreads();
    for (int s = 64; s > 0; s >>= 1) {
        if (tid < s) red[tid] += red[tid+s];
        __syncthreads();
    }
    float inv = 1.0f / red[0];
    row[tid] = make_float4(e0*inv, e1*inv, e2*inv, e3*inv);
}

// ---------------- epilogue ----------------
__global__ void epilogue_kernel(const float* __restrict__ trans)
{
    int i = blockIdx.x;
    int tid = threadIdx.x;
    __shared__ float s_cos[96], s_sin[96], s_tr[3];
    if (tid < 96) { s_cos[tid] = g_cosb[i*96+tid]; s_sin[tid] = g_sinb[i*96+tid]; }
    if (tid >= 128 && tid < 131) s_tr[tid-128] = trans[i*3 + tid - 128];
    __syncthreads();

    for (int idx = tid; idx < HN*64; idx += blockDim.x) {
        int h = idx / 64, f = idx % 64;
        int kb = f & 31;
        float acc = 0.f;
        long long o = ((long long)h*LN + i)*FV;
#pragma unroll
        for (int c = 0; c < 3; c++) {
            float o1 = g_OV[o + c*64 + f];
            float o2 = g_OV[o + c*64 + ((f < 32) ? (f+32) : (f-32))];
            float cs = s_cos[c*32 + kb], sn = s_sin[c*32 + kb];
            acc += (f < 32) ? (o1*cs + o2*sn) : (o1*cs - o2*sn);
        }
        g_feat[(long long)i*NFEAT + h*64 + f] = acc * (1.0f/3.0f);
    }
    for (int idx = tid; idx < HN*8; idx += blockDim.x) {
        int h = idx / 8, p = idx % 8;
        long long o = ((long long)h*LN + i)*FV + 192 + p*3;
        float ox = g_OV[o+0] - s_tr[0];
        float oy = g_OV[o+1] - s_tr[1];
        float oz = g_OV[o+2] - s_tr[2];
        long long fb = (long long)i*NFEAT + 512;
        g_feat[fb + 0*64 + h*8 + p] = ox;
        g_feat[fb + 1*64 + h*8 + p] = oy;
        g_feat[fb + 2*64 + h*8 + p] = oz;
        g_feat[fb + 192  + h*8 + p] = sqrtf(ox*ox + oy*oy + oz*oz + 1e-6f);
    }
    for (int idx = tid; idx < HN*96; idx += blockDim.x) {
        int h = idx / 96, ck = idx % 96;
        int c = ck / 32, k = ck % 32;
        long long o = ((long long)h*LN + i)*FV;
        float Pc = g_OV[o + 216 + ck];
        float Ps = g_OV[o + 312 + ck];
        float ci = s_cos[ck], si = s_sin[ck];
        long long fb = (long long)i*NFEAT + 768 + h*192 + c*64 + k;
        g_feat[fb]      = ci*Pc + si*Ps;
        g_feat[fb + 32] = ci*Ps - si*Pc;
    }
}

// ---------------- split-K reduce ----------------
__global__ void reduce_out(float* __restrict__ out, const float* __restrict__ b_pt)
{
    int i = blockIdx.x * 256 + threadIdx.x;
    const int S = LN * 512;
    float v = b_pt[i & 511] + g_part[i] + g_part[i + S] + g_part[i + 2*S] + g_part[i + 3*S];
    out[i] = v;
}

// ---------------- host launcher ----------------
static void launch_g(cudaStream_t st,
                     const float* A, int lda, long long sA,
                     const float* B, int ldb, long long sB,
                     float* C, int ldc, long long sC,
                     int M, int N, int K, int batch,
                     int transB, int accum, const float* bias, int nterms)
{
    dim3 grid(N / 64, M / 128, batch);
    if (transB) {
        if (nterms == 3)
            gemm3x<1,3><<<grid, 256, 0, st>>>(A, lda, sA, B, ldb, sB, C, ldc, sC, K, accum, bias);
        else
            gemm3x<1,2><<<grid, 256, 0, st>>>(A, lda, sA, B, ldb, sB, C, ldc, sC, K, accum, bias);
    } else {
        if (nterms == 3)
            gemm3x<0,3><<<grid, 256, 0, st>>>(A, lda, sA, B, ldb, sB, C, ldc, sC, K, accum, bias);
        else
            gemm3x<0,2><<<grid, 256, 0, st>>>(A, lda, sA, B, ldb, sB, C, ldc, sC, K, accum, bias);
    }
}

extern "C" void kernel_launch(void* const* d_in, const int* in_sizes, int n_in,
                              void* d_out, int out_size)
{
    (void)in_sizes; (void)n_in; (void)out_size;
    const float* x       = (const float*)d_in[0];
    const float* z       = (const float*)d_in[1];
    const float* trans   = (const float*)d_in[3];
    const float* w_q     = (const float*)d_in[5];
    const float* w_k     = (const float*)d_in[6];
    const float* w_v     = (const float*)d_in[7];
    const float* w_o     = (const float*)d_in[8];
    const float* w_b     = (const float*)d_in[9];
    const float* w_qpts  = (const float*)d_in[10];
    const float* b_qpts  = (const float*)d_in[11];
    const float* w_kvpts = (const float*)d_in[12];
    const float* b_kvpts = (const float*)d_in[13];
    const float* head_w  = (const float*)d_in[14];
    const float* w_pt    = (const float*)d_in[15];
    const float* b_pt    = (const float*)d_in[16];
    const float* w_rq    = (const float*)d_in[17];
    const float* w_r     = (const float*)d_in[18];
    float* out = (float*)d_out;

    float *p_Win, *p_bvec, *p_Wout, *p_proj, *p_Qf, *p_Kf, *p_Vf, *p_attn, *p_OV, *p_feat, *p_part;
    cudaGetSymbolAddress((void**)&p_Win, g_Win);
    cudaGetSymbolAddress((void**)&p_bvec, g_bvec);
    cudaGetSymbolAddress((void**)&p_Wout, g_Wout);
    cudaGetSymbolAddress((void**)&p_proj, g_proj);
    cudaGetSymbolAddress((void**)&p_Qf, g_Qf);
    cudaGetSymbolAddress((void**)&p_Kf, g_Kf);
    cudaGetSymbolAddress((void**)&p_Vf, g_Vf);
    cudaGetSymbolAddress((void**)&p_attn, g_attn);
    cudaGetSymbolAddress((void**)&p_OV, g_OV);
    cudaGetSymbolAddress((void**)&p_feat, g_feat);
    cudaGetSymbolAddress((void**)&p_part, g_part);

    // One-time side-stream + fork/join events (created on the uncaptured
    // correctness call; reused identically on every call -> deterministic).
    static cudaStream_t s2 = nullptr;
    static cudaEvent_t evFork = nullptr, evJoin = nullptr;
    if (!s2) {
        cudaStreamCreateWithFlags(&s2, cudaStreamNonBlocking);
        cudaEventCreateWithFlags(&evFork, cudaEventDisableTiming);
        cudaEventCreateWithFlags(&evJoin, cudaEventDisableTiming);
    }

    // ---- fork: s2 runs zbias + Wout staging, concurrent with main chain ----
    cudaEventRecord(evFork, 0);
    cudaStreamWaitEvent(s2, evFork, 0);
    zbias_kernel<<<LN*LN/256, 256, 0, s2>>>(z, w_b);
    cudaMemcpyAsync(p_Wout,            w_o,  512*512*sizeof(float),  cudaMemcpyDeviceToDevice, s2);
    cudaMemcpyAsync(p_Wout + 512*512,  w_pt, 256*512*sizeof(float),  cudaMemcpyDeviceToDevice, s2);
    cudaMemcpyAsync(p_Wout + 768*512,  w_r,  1536*512*sizeof(float), cudaMemcpyDeviceToDevice, s2);
    cudaEventRecord(evJoin, s2);

    // ---- main chain (default stream) ----
    // 0) pack fused projection weights
    pack_win<<<(512*NPROJ + 255)/256, 256>>>(w_q, w_k, w_v, w_rq, w_qpts, w_kvpts,
                                             b_qpts, b_kvpts);

    // 1) input projections:
    //    bulk q/k/v/rq cols (random-sign products) -> 2-term; no bias needed
    launch_g(0, x, 512, 0, p_Win, NPROJ, 0, p_proj, NPROJ, 0,
             512, 3072, 512, 1, 0, 0, nullptr, 2);
    //    point cols (feed qsq/d2 cancellation) -> full 3-term + bias
    launch_g(0, x, 512, 0, p_Win + 3072, NPROJ, 0, p_proj + 3072, NPROJ, 0,
             512, 384, 512, 1, 0, 0, p_bvec + 3072, 3);

    // 2) feature construction
    build_features_kernel<<<512, 256>>>(trans, head_w);

    // ---- join: logits accumulates onto z bias; Wout staged for step 8 ----
    cudaStreamWaitEvent(0, evJoin, 0);

    // 4) logits: Qf @ Kf^T (3-term); K=400 covers all non-zero dims (398)
    launch_g(0, p_Qf, FQ, (long long)LN*FQ, p_Kf, FQ, (long long)LN*FQ,
             p_attn, LN, (long long)LN*LN, 512, 512, 400, HN, 1, 1, 0, 3);

    // 5) softmax
    softmax_kernel<<<HN*LN, 128>>>();

    // 6) value side (3-term: vp magnitudes + -trans cancellation)
    launch_g(0, p_attn, LN, (long long)LN*LN, p_Vf, FV, (long long)LN*FV,
             p_OV, FV, (long long)LN*FV, 512, FV, 512, HN, 0, 0, 0, 3);

    // 7) epilogue features
    epilogue_kernel<<<512, 256>>>(trans);

    // 8) output projection (2-term, split-K x4) + reduce
    launch_g(0, p_feat, NFEAT, 576, p_Wout, 512, (long long)576*512,
             p_part, 512, (long long)LN*512, 512, 512, 576, 4, 0, 0, 0, 2);
    reduce_out<<<LN*512/256, 256>>>(out, b_pt);
}

// round 12
// speedup vs baseline: 1.0984x; 1.0984x over previous
#include <cuda_runtime.h>
#include <math.h>

#define HN 8
#define LN 512
#define FQ 416
#define FV 448
#define NPROJ 3456
#define NFEAT 2304

// ---------------- scratch (static __device__, no allocation) ----------------
__device__ float g_Win[512*NPROJ];
__device__ float g_bvec[NPROJ];
__device__ float g_Wout[NFEAT*512];
__device__ float g_proj[LN*NPROJ];
__device__ float g_cosb[LN*96];
__device__ float g_sinb[LN*96];
__device__ float g_Qf[HN*LN*FQ];
__device__ float g_Kf[HN*LN*FQ];
__device__ float g_Vf[HN*LN*FV];
__device__ float g_attn[HN*LN*LN];
__device__ float g_OV[HN*LN*FV];
__device__ float g_feat[LN*NFEAT];
__device__ float g_part[4*LN*512];

// ---------------- helpers ----------------
__device__ __forceinline__ float tf32f(float x) {
    unsigned u;
    asm("cvt.rna.tf32.f32 %0, %1;" : "=r"(u) : "f"(x));
    return __uint_as_float(u);
}

__device__ __forceinline__ void mma_tf32(float4& d, const unsigned* a,
                                         unsigned b0, unsigned b1) {
    asm volatile(
        "mma.sync.aligned.m16n8k8.row.col.f32.tf32.tf32.f32 "
        "{%0,%1,%2,%3},{%4,%5,%6,%7},{%8,%9},{%0,%1,%2,%3};"
        : "+f"(d.x), "+f"(d.y), "+f"(d.z), "+f"(d.w)
        : "r"(a[0]), "r"(a[1]), "r"(a[2]), "r"(a[3]), "r"(b0), "r"(b1));
}

// ------------- split-TF32 tensor-core GEMM: 128x64 tile --------------------
// C[M,N] = [C +] A[M,K] @ (TRANSB ? B[N,K]^T : B[K,N]) [+ bias].
// A pre-split (hi/lo smem tiles at staging); B raw fp32 in smem.
// MODE=3: acc += al*bh + ah*bl + ah*bh   (~fp32 accuracy)
// MODE=2: acc += al*bh + ah*bh           (B low bits dropped, ~half-tf32 rel)
// MODE=0: mixed -- 3-term iff this block's col0 >= thresh (block-uniform).
// Smem: 2*2*16*136*4 + 2*16*72*4 = 44032 B (< 48KB static limit).
// M%128==0, N%64==0, K%16==0. All pointers float4-aligned.
template<int TRANSB, int MODE>
__global__ void __launch_bounds__(256)
gemm3x(const float* __restrict__ A, int lda, long long sA,
       const float* __restrict__ B, int ldb, long long sB,
       float* __restrict__ C, int ldc, long long sC,
       int K, int accum, const float* __restrict__ bias, int thresh)
{
    __shared__ float Ah[2][16][136];  // [k][m] hi, stride%32==8 -> conflict-free
    __shared__ float Al[2][16][136];  // [k][m] lo
    __shared__ float Bs[2][16][72];   // [k][n] raw fp32
    const int bz = blockIdx.z;
    A += (long long)bz * sA;
    B += (long long)bz * sB;
    C += (long long)bz * sC;
    const int row0 = blockIdx.y * 128, col0 = blockIdx.x * 64;
    const bool use3 = (MODE == 3) || (MODE == 0 && col0 >= thresh);
    const int tid = threadIdx.x;
    const int lane = tid & 31, wid = tid >> 5;
    const int g = lane >> 2, tig = lane & 3;
    const int wm = (wid & 3) * 32, wn = (wid >> 2) * 32;

    const int am = tid >> 2, akq = tid & 3;
    const float* pA0 = A + (long long)(row0 + am) * lda + akq * 4;
    const float* pA1 = A + (long long)(row0 + am + 64) * lda + akq * 4;
    const float* pB;
    int bn = 0, bkq = 0, bkk = 0, bnq = 0;
    if (TRANSB) {
        bn = tid >> 2; bkq = tid & 3;
        pB = B + (long long)(col0 + bn) * ldb + bkq * 4;
    } else {
        bkk = tid >> 4; bnq = tid & 15;
        pB = B + (long long)bkk * ldb + col0 + bnq * 4;
    }

    float4 acc[2][4];
#pragma unroll
    for (int mf = 0; mf < 2; mf++)
#pragma unroll
        for (int nf = 0; nf < 4; nf++) acc[mf][nf] = make_float4(0.f,0.f,0.f,0.f);

    float4 ra0 = *(const float4*)pA0;
    float4 ra1 = *(const float4*)pA1;
    float4 rb  = *(const float4*)pB;

#define SPLIT_STORE_A(bf, kk, mm, v)                                       \
    do { float _h = tf32f(v); Ah[bf][kk][mm] = _h;                         \
         Al[bf][kk][mm] = tf32f((v) - _h); } while (0)

#define STORE_TILE(bf)                                                     \
    do {                                                                   \
        SPLIT_STORE_A(bf, akq*4+0, am,    ra0.x);                          \
        SPLIT_STORE_A(bf, akq*4+1, am,    ra0.y);                          \
        SPLIT_STORE_A(bf, akq*4+2, am,    ra0.z);                          \
        SPLIT_STORE_A(bf, akq*4+3, am,    ra0.w);                          \
        SPLIT_STORE_A(bf, akq*4+0, am+64, ra1.x);                          \
        SPLIT_STORE_A(bf, akq*4+1, am+64, ra1.y);                          \
        SPLIT_STORE_A(bf, akq*4+2, am+64, ra1.z);                          \
        SPLIT_STORE_A(bf, akq*4+3, am+64, ra1.w);                          \
        if (TRANSB) {                                                      \
            Bs[bf][bkq*4+0][bn] = rb.x;                                    \
            Bs[bf][bkq*4+1][bn] = rb.y;                                    \
            Bs[bf][bkq*4+2][bn] = rb.z;                                    \
            Bs[bf][bkq*4+3][bn] = rb.w;                                    \
        } else {                                                           \
            *(float4*)&Bs[bf][bkk][bnq*4] = rb;                            \
        }                                                                  \
    } while (0)

#define COMPUTE_TILE(bf)                                                   \
    do {                                                                   \
        _Pragma("unroll")                                                  \
        for (int ks = 0; ks < 2; ks++) {                                   \
            const int k0 = ks * 8;                                         \
            unsigned ah[2][4], al[2][4], bh[4][2], bl[4][2];               \
            _Pragma("unroll")                                              \
            for (int mf = 0; mf < 2; mf++) {                               \
                int m0 = wm + mf * 16;                                     \
                ah[mf][0] = __float_as_uint(Ah[bf][k0+tig  ][m0+g  ]);     \
                ah[mf][1] = __float_as_uint(Ah[bf][k0+tig  ][m0+g+8]);     \
                ah[mf][2] = __float_as_uint(Ah[bf][k0+tig+4][m0+g  ]);     \
                ah[mf][3] = __float_as_uint(Ah[bf][k0+tig+4][m0+g+8]);     \
                al[mf][0] = __float_as_uint(Al[bf][k0+tig  ][m0+g  ]);     \
                al[mf][1] = __float_as_uint(Al[bf][k0+tig  ][m0+g+8]);     \
                al[mf][2] = __float_as_uint(Al[bf][k0+tig+4][m0+g  ]);     \
                al[mf][3] = __float_as_uint(Al[bf][k0+tig+4][m0+g+8]);     \
            }                                                              \
            _Pragma("unroll")                                              \
            for (int nf = 0; nf < 4; nf++) {                               \
                int n0 = wn + nf * 8;                                      \
                float w0 = Bs[bf][k0+tig  ][n0+g];                         \
                float w1 = Bs[bf][k0+tig+4][n0+g];                         \
                float h0 = tf32f(w0), h1 = tf32f(w1);                      \
                bh[nf][0] = __float_as_uint(h0);                           \
                bh[nf][1] = __float_as_uint(h1);                           \
                if (MODE != 2 && use3) {                                   \
                    bl[nf][0] = __float_as_uint(tf32f(w0 - h0));           \
                    bl[nf][1] = __float_as_uint(tf32f(w1 - h1));           \
                } else {                                                   \
                    bl[nf][0] = 0; bl[nf][1] = 0;                          \
                }                                                          \
            }                                                              \
            _Pragma("unroll")                                              \
            for (int mf = 0; mf < 2; mf++)                                 \
                _Pragma("unroll")                                          \
                for (int nf = 0; nf < 4; nf++) {                           \
                    mma_tf32(acc[mf][nf], al[mf], bh[nf][0], bh[nf][1]);   \
                    if (MODE != 2 && use3)                                 \
                        mma_tf32(acc[mf][nf], ah[mf], bl[nf][0], bl[nf][1]); \
                    mma_tf32(acc[mf][nf], ah[mf], bh[nf][0], bh[nf][1]);   \
                }                                                          \
        }                                                                  \
    } while (0)

    STORE_TILE(0);
    __syncthreads();

    const int T = K >> 4;
    int buf = 0;
#pragma unroll 1
    for (int t = 1; t < T; t++) {
        pA0 += 16; pA1 += 16;
        ra0 = *(const float4*)pA0;
        ra1 = *(const float4*)pA1;
        pB += TRANSB ? 16 : (long long)16 * ldb;
        rb = *(const float4*)pB;

        COMPUTE_TILE(buf);
        int nb = buf ^ 1;
        STORE_TILE(nb);
        __syncthreads();
        buf = nb;
    }
    COMPUTE_TILE(buf);

    // epilogue: (x,y) -> (row, col..col+1); (z,w) -> (row+8, col..col+1)
#pragma unroll
    for (int mf = 0; mf < 2; mf++) {
#pragma unroll
        for (int nf = 0; nf < 4; nf++) {
            int row = row0 + wm + mf*16 + g;
            int col = col0 + wn + nf*8 + tig*2;
            long long i1 = (long long)row * ldc + col;
            long long i2 = (long long)(row + 8) * ldc + col;
            float4 v = acc[mf][nf];
            if (bias) {
                float b0 = bias[col], b1 = bias[col+1];
                v.x += b0; v.y += b1; v.z += b0; v.w += b1;
            }
            if (accum) {
                float2 o1 = *(float2*)(C + i1);
                float2 o2 = *(float2*)(C + i2);
                v.x += o1.x; v.y += o1.y; v.z += o2.x; v.w += o2.y;
            }
            *(float2*)(C + i1) = make_float2(v.x, v.y);
            *(float2*)(C + i2) = make_float2(v.z, v.w);
        }
    }
#undef STORE_TILE
#undef COMPUTE_TILE
#undef SPLIT_STORE_A
}

// ---------------- weight packing ----------------
__global__ void pack_win(const float* __restrict__ wq, const float* __restrict__ wk,
                         const float* __restrict__ wv, const float* __restrict__ wrq,
                         const float* __restrict__ wqp, const float* __restrict__ wkp,
                         const float* __restrict__ bqp, const float* __restrict__ bkp)
{
    int idx = blockIdx.x * 256 + threadIdx.x;
    if (idx < NPROJ) {
        float bv = 0.f;
        if (idx >= 3168) bv = bkp[idx - 3168];
        else if (idx >= 3072) bv = bqp[idx - 3072];
        g_bvec[idx] = bv;
    }
    if (idx >= 512 * NPROJ) return;
    int k = idx / NPROJ, c = idx % NPROJ;
    float v;
    if (c < 512)       v = wq[k*512 + c];
    else if (c < 1024) v = wk[k*512 + c - 512];
    else if (c < 1536) v = wv[k*512 + c - 1024];
    else if (c < 3072) v = wrq[k*1536 + c - 1536];
    else if (c < 3168) v = wqp[k*96 + c - 3072];
    else               v = wkp[k*288 + c - 3168];
    g_Win[idx] = v;
}

// ---------------- feature construction ----------------
// Qf/Kf layout: [0:192) rope | [192:384) remb cos/sin | [384:396) points
//               | 396 qsq/one | 397 one/ksq | [398:416) zero pad
__global__ void build_features_kernel(const float* __restrict__ trans,
                                      const float* __restrict__ head_w)
{
    int i = blockIdx.x;
    int tid = threadIdx.x;
    __shared__ float s_cos[96], s_sin[96], s_tr[3], s_hw[HN];
    if (tid < 3) s_tr[tid] = trans[i*3 + tid];
    if (tid >= 32 && tid < 32 + HN)
        s_hw[tid-32] = log1pf(expf(head_w[tid-32])) * 0.23570226039551584f;
    __syncthreads();
    if (tid < 96) {
        int c = tid / 32, k = tid % 32;
        float freq = 6.283185307179586f * expf(-(float)k * (logf(100.0f) / 31.0f));
        float sv, cv;
        sincosf(s_tr[c] * freq, &sv, &cv);
        s_cos[tid] = cv; s_sin[tid] = sv;
        g_cosb[i*96 + tid] = cv; g_sinb[i*96 + tid] = sv;
    }
    __syncthreads();

    const float* pr = g_proj + (long long)i * NPROJ;

    for (int idx = tid; idx < HN*192; idx += blockDim.x) {
        int h = idx / 192, d = idx % 192;
        int c = d / 64, f = d % 64;
        int kb = c*32 + (f & 31);
        float cs = s_cos[kb], sn = s_sin[kb];
        int col  = h*64 + f;
        int colp = h*64 + ((f < 32) ? (f + 32) : (f - 32));
        float sgn = (f < 32) ? -1.f : 1.f;
        float qv = pr[col],        q2 = pr[colp];
        float kv = pr[512 + col],  k2 = pr[colp + 512];
        float vv = pr[1024 + col], v2 = pr[1024 + colp];
        long long qo = ((long long)h*LN + i)*FQ + d;
        long long vo = ((long long)h*LN + i)*FV + d;
        g_Qf[qo] = (qv*cs + sgn*q2*sn) * 0.125f;
        g_Kf[qo] = kv*cs + sgn*k2*sn;
        g_Vf[vo] = vv*cs + sgn*v2*sn;
    }
    for (int idx = tid; idx < HN*12; idx += blockDim.x) {
        int h = idx / 12, t = idx % 12;
        int p = t / 3, c = t % 3;
        float qp = pr[3072 + c*32 + h*4  + p] + s_tr[c];
        float kp = pr[3168 + c*96 + h*12 + p] + s_tr[c];
        long long o = ((long long)h*LN + i)*FQ + 384 + t;
        g_Qf[o] = s_hw[h] * qp;
        g_Kf[o] = kp;
    }
    for (int idx = tid; idx < HN*24; idx += blockDim.x) {
        int h = idx / 24, t = idx % 24;
        int p = t / 3, c = t % 3;
        g_Vf[((long long)h*LN + i)*FV + 192 + t] =
            pr[3168 + c*96 + h*12 + 4 + p] + s_tr[c];
    }
    for (int idx = tid; idx < HN*96; idx += blockDim.x) {
        int h = idx / 96, ck = idx % 96;
        int c = ck / 32, k = ck % 32;
        float rqc = pr[1536 + h*192 + c*64 + k];
        float rqs = pr[1536 + h*192 + c*64 + 32 + k];
        float ci = s_cos[ck], si = s_sin[ck];
        const float inv = 0.07216878364870322f; // 1/sqrt(192)
        long long qo = ((long long)h*LN + i)*FQ;
        g_Qf[qo + 192 + ck] = (rqc*ci - rqs*si) * inv;
        g_Qf[qo + 288 + ck] = (rqc*si + rqs*ci) * inv;
        g_Kf[qo + 192 + ck] = ci;
        g_Kf[qo + 288 + ck] = si;
        long long vo = ((long long)h*LN + i)*FV;
        g_Vf[vo + 216 + ck] = ci;
        g_Vf[vo + 312 + ck] = si;
    }
    for (int h = tid; h < HN; h += blockDim.x) {
        float qsq = 0.f, ksq = 0.f;
        for (int p = 0; p < 4; p++)
            for (int c = 0; c < 3; c++) {
                float qv = pr[3072 + c*32 + h*4  + p] + s_tr[c];
                float kv = pr[3168 + c*96 + h*12 + p] + s_tr[c];
                qsq += qv*qv; ksq += kv*kv;
            }
        long long qo = ((long long)h*LN + i)*FQ;
        g_Qf[qo + 396] = -0.5f * s_hw[h] * qsq;
        g_Qf[qo + 397] = -0.5f * s_hw[h];
        g_Kf[qo + 396] = 1.f;
        g_Kf[qo + 397] = ksq;
        for (int t2 = 398; t2 < FQ; t2++) { g_Qf[qo + t2] = 0.f; g_Kf[qo + t2] = 0.f; }
        long long vo = ((long long)h*LN + i)*FV;
        for (int t2 = 408; t2 < FV; t2++) g_Vf[vo + t2] = 0.f;
    }
}

// ---------------- z pair-bias: shuffle-free, smem-tiled --------------------
__global__ void __launch_bounds__(256)
zbias_kernel(const float* __restrict__ z, const float* __restrict__ w_b)
{
    __shared__ float zs[256*36];
    __shared__ float wT[8*128];
    const int tid = threadIdx.x;
    const long long P0 = (long long)blockIdx.x * 256;

    for (int e = tid; e < 1024; e += 256) {
        int h = e >> 7, c = e & 127;
        wT[e] = w_b[c*8 + h];
    }

    float acc[8] = {0.f,0.f,0.f,0.f,0.f,0.f,0.f,0.f};

#pragma unroll
    for (int chunk = 0; chunk < 4; chunk++) {
        const int c0 = chunk * 32;
        __syncthreads();
#pragma unroll
        for (int k = 0; k < 8; k++) {
            int e = k*256 + tid;
            int pp = e >> 3, cq = e & 7;
            float4 v = *(const float4*)(z + (P0 + pp)*128 + c0 + cq*4);
            *(float4*)&zs[pp*36 + cq*4] = v;
        }
        __syncthreads();
#pragma unroll
        for (int s = 0; s < 8; s++) {
            float4 zv = *(const float4*)&zs[tid*36 + s*4];
            int c = c0 + s*4;
#pragma unroll
            for (int h = 0; h < 8; h++) {
                float4 wv = *(const float4*)&wT[h*128 + c];
                acc[h] += zv.x*wv.x + zv.y*wv.y + zv.z*wv.z + zv.w*wv.w;
            }
        }
    }

    const int i = (int)((P0 + tid) >> 9);
    const int j = (int)((P0 + tid) & 511);
#pragma unroll
    for (int h = 0; h < 8; h++)
        g_attn[((long long)h*LN + i)*LN + j] = acc[h];
}

// ---------------- softmax over j ----------------
__global__ void softmax_kernel()
{
    int r = blockIdx.x;
    int tid = threadIdx.x; // 128
    float4* row = (float4*)(g_attn + (long long)r * LN);
    float4 v = row[tid];
    __shared__ float red[128];
    float m = fmaxf(fmaxf(v.x, v.y), fmaxf(v.z, v.w));
    red[tid] = m; __syncthreads();
    for (int s = 64; s > 0; s >>= 1) {
        if (tid < s) red[tid] = fmaxf(red[tid], red[tid+s]);
        __syncthreads();
    }
    float M = red[0]; __syncthreads();
    float e0 = expf(v.x - M), e1 = expf(v.y - M);
    float e2 = expf(v.z - M), e3 = expf(v.w - M);
    red[tid] = e0 + e1 + e2 + e3; __syncthreads();
    for (int s = 64; s > 0; s >>= 1) {
        if (tid < s) red[tid] += red[tid+s];
        __syncthreads();
    }
    float inv = 1.0f / red[0];
    row[tid] = make_float4(e0*inv, e1*inv, e2*inv, e3*inv);
}

// ---------------- epilogue ----------------
__global__ void epilogue_kernel(const float* __restrict__ trans)
{
    int i = blockIdx.x;
    int tid = threadIdx.x;
    __shared__ float s_cos[96], s_sin[96], s_tr[3];
    if (tid < 96) { s_cos[tid] = g_cosb[i*96+tid]; s_sin[tid] = g_sinb[i*96+tid]; }
    if (tid >= 128 && tid < 131) s_tr[tid-128] = trans[i*3 + tid - 128];
    __syncthreads();

    for (int idx = tid; idx < HN*64; idx += blockDim.x) {
        int h = idx / 64, f = idx % 64;
        int kb = f & 31;
        float acc = 0.f;
        long long o = ((long long)h*LN + i)*FV;
#pragma unroll
        for (int c = 0; c < 3; c++) {
            float o1 = g_OV[o + c*64 + f];
            float o2 = g_OV[o + c*64 + ((f < 32) ? (f+32) : (f-32))];
            float cs = s_cos[c*32 + kb], sn = s_sin[c*32 + kb];
            acc += (f < 32) ? (o1*cs + o2*sn) : (o1*cs - o2*sn);
        }
        g_feat[(long long)i*NFEAT + h*64 + f] = acc * (1.0f/3.0f);
    }
    for (int idx = tid; idx < HN*8; idx += blockDim.x) {
        int h = idx / 8, p = idx % 8;
        long long o = ((long long)h*LN + i)*FV + 192 + p*3;
        float ox = g_OV[o+0] - s_tr[0];
        float oy = g_OV[o+1] - s_tr[1];
        float oz = g_OV[o+2] - s_tr[2];
        long long fb = (long long)i*NFEAT + 512;
        g_feat[fb + 0*64 + h*8 + p] = ox;
        g_feat[fb + 1*64 + h*8 + p] = oy;
        g_feat[fb + 2*64 + h*8 + p] = oz;
        g_feat[fb + 192  + h*8 + p] = sqrtf(ox*ox + oy*oy + oz*oz + 1e-6f);
    }
    for (int idx = tid; idx < HN*96; idx += blockDim.x) {
        int h = idx / 96, ck = idx % 96;
        int c = ck / 32, k = ck % 32;
        long long o = ((long long)h*LN + i)*FV;
        float Pc = g_OV[o + 216 + ck];
        float Ps = g_OV[o + 312 + ck];
        float ci = s_cos[ck], si = s_sin[ck];
        long long fb = (long long)i*NFEAT + 768 + h*192 + c*64 + k;
        g_feat[fb]      = ci*Pc + si*Ps;
        g_feat[fb + 32] = ci*Ps - si*Pc;
    }
}

// ---------------- split-K reduce ----------------
__global__ void reduce_out(float* __restrict__ out, const float* __restrict__ b_pt)
{
    int i = blockIdx.x * 256 + threadIdx.x;
    const int S = LN * 512;
    float v = b_pt[i & 511] + g_part[i] + g_part[i + S] + g_part[i + 2*S] + g_part[i + 3*S];
    out[i] = v;
}

// ---------------- host launcher ----------------
// mode: 2 = 2-term, 3 = 3-term, 0 = mixed (3-term iff col0 >= thresh)
static void launch_g(cudaStream_t st,
                     const float* A, int lda, long long sA,
                     const float* B, int ldb, long long sB,
                     float* C, int ldc, long long sC,
                     int M, int N, int K, int batch,
                     int transB, int accum, const float* bias,
                     int mode, int thresh)
{
    dim3 grid(N / 64, M / 128, batch);
    if (transB) {
        if (mode == 3)      gemm3x<1,3><<<grid, 256, 0, st>>>(A, lda, sA, B, ldb, sB, C, ldc, sC, K, accum, bias, thresh);
        else if (mode == 2) gemm3x<1,2><<<grid, 256, 0, st>>>(A, lda, sA, B, ldb, sB, C, ldc, sC, K, accum, bias, thresh);
        else                gemm3x<1,0><<<grid, 256, 0, st>>>(A, lda, sA, B, ldb, sB, C, ldc, sC, K, accum, bias, thresh);
    } else {
        if (mode == 3)      gemm3x<0,3><<<grid, 256, 0, st>>>(A, lda, sA, B, ldb, sB, C, ldc, sC, K, accum, bias, thresh);
        else if (mode == 2) gemm3x<0,2><<<grid, 256, 0, st>>>(A, lda, sA, B, ldb, sB, C, ldc, sC, K, accum, bias, thresh);
        else                gemm3x<0,0><<<grid, 256, 0, st>>>(A, lda, sA, B, ldb, sB, C, ldc, sC, K, accum, bias, thresh);
    }
}

extern "C" void kernel_launch(void* const* d_in, const int* in_sizes, int n_in,
                              void* d_out, int out_size)
{
    (void)in_sizes; (void)n_in; (void)out_size;
    const float* x       = (const float*)d_in[0];
    const float* z       = (const float*)d_in[1];
    const float* trans   = (const float*)d_in[3];
    const float* w_q     = (const float*)d_in[5];
    const float* w_k     = (const float*)d_in[6];
    const float* w_v     = (const float*)d_in[7];
    const float* w_o     = (const float*)d_in[8];
    const float* w_b     = (const float*)d_in[9];
    const float* w_qpts  = (const float*)d_in[10];
    const float* b_qpts  = (const float*)d_in[11];
    const float* w_kvpts = (const float*)d_in[12];
    const float* b_kvpts = (const float*)d_in[13];
    const float* head_w  = (const float*)d_in[14];
    const float* w_pt    = (const float*)d_in[15];
    const float* b_pt    = (const float*)d_in[16];
    const float* w_rq    = (const float*)d_in[17];
    const float* w_r     = (const float*)d_in[18];
    float* out = (float*)d_out;

    float *p_Win, *p_bvec, *p_Wout, *p_proj, *p_Qf, *p_Kf, *p_Vf, *p_attn, *p_OV, *p_feat, *p_part;
    cudaGetSymbolAddress((void**)&p_Win, g_Win);
    cudaGetSymbolAddress((void**)&p_bvec, g_bvec);
    cudaGetSymbolAddress((void**)&p_Wout, g_Wout);
    cudaGetSymbolAddress((void**)&p_proj, g_proj);
    cudaGetSymbolAddress((void**)&p_Qf, g_Qf);
    cudaGetSymbolAddress((void**)&p_Kf, g_Kf);
    cudaGetSymbolAddress((void**)&p_Vf, g_Vf);
    cudaGetSymbolAddress((void**)&p_attn, g_attn);
    cudaGetSymbolAddress((void**)&p_OV, g_OV);
    cudaGetSymbolAddress((void**)&p_feat, g_feat);
    cudaGetSymbolAddress((void**)&p_part, g_part);

    // One-time side-stream + fork/join events (created on the uncaptured
    // correctness call; reused identically on every call -> deterministic).
    static cudaStream_t s2 = nullptr;
    static cudaEvent_t evFork = nullptr, evJoin = nullptr;
    if (!s2) {
        cudaStreamCreateWithFlags(&s2, cudaStreamNonBlocking);
        cudaEventCreateWithFlags(&evFork, cudaEventDisableTiming);
        cudaEventCreateWithFlags(&evJoin, cudaEventDisableTiming);
    }

    // ---- fork: s2 runs zbias + Wout staging, concurrent with main chain ----
    cudaEventRecord(evFork, 0);
    cudaStreamWaitEvent(s2, evFork, 0);
    zbias_kernel<<<LN*LN/256, 256, 0, s2>>>(z, w_b);
    cudaMemcpyAsync(p_Wout,            w_o,  512*512*sizeof(float),  cudaMemcpyDeviceToDevice, s2);
    cudaMemcpyAsync(p_Wout + 512*512,  w_pt, 256*512*sizeof(float),  cudaMemcpyDeviceToDevice, s2);
    cudaMemcpyAsync(p_Wout + 768*512,  w_r,  1536*512*sizeof(float), cudaMemcpyDeviceToDevice, s2);
    cudaEventRecord(evJoin, s2);

    // ---- main chain (default stream) ----
    // 0) pack fused projection weights
    pack_win<<<(512*NPROJ + 255)/256, 256>>>(w_q, w_k, w_v, w_rq, w_qpts, w_kvpts,
                                             b_qpts, b_kvpts);

    // 1) input projections: ONE launch, mixed precision per column block:
    //    cols < 3072 (q/k/v/rq, random-sign) -> 2-term;
    //    cols >= 3072 (points, feed qsq/d2 cancellation) -> 3-term.
    //    bvec is zero below 3072, so fused bias is a no-op there.
    launch_g(0, x, 512, 0, p_Win, NPROJ, 0, p_proj, NPROJ, 0,
             512, NPROJ, 512, 1, 0, 0, p_bvec, 0, 3072);

    // 2) feature construction
    build_features_kernel<<<512, 256>>>(trans, head_w);

    // ---- join: logits accumulates onto z bias; Wout staged for step 8 ----
    cudaStreamWaitEvent(0, evJoin, 0);

    // 4) logits: Qf @ Kf^T (3-term); K=400 covers all non-zero dims (398)
    launch_g(0, p_Qf, FQ, (long long)LN*FQ, p_Kf, FQ, (long long)LN*FQ,
             p_attn, LN, (long long)LN*LN, 512, 512, 400, HN, 1, 1, 0, 3, 0);

    // 5) softmax
    softmax_kernel<<<HN*LN, 128>>>();

    // 6) value side (3-term: vp magnitudes + -trans cancellation)
    launch_g(0, p_attn, LN, (long long)LN*LN, p_Vf, FV, (long long)LN*FV,
             p_OV, FV, (long long)LN*FV, 512, FV, 512, HN, 0, 0, 0, 3, 0);

    // 7) epilogue features
    epilogue_kernel<<<512, 256>>>(trans);

    // 8) output projection (2-term, split-K x4) + reduce
    launch_g(0, p_feat, NFEAT, 576, p_Wout, 512, (long long)576*512,
             p_part, 512, (long long)LN*512, 512, 512, 576, 4, 0, 0, 0, 2, 0);
    reduce_out<<<LN*512/256, 256>>>(out, b_pt);
}

// round 13
// speedup vs baseline: 1.4665x; 1.3352x over previous
#include <cuda_runtime.h>
#include <cuda_bf16.h>
#include <math.h>

#define HN 8
#define LN 512
#define FQ 416
#define FV 448
#define NPROJ 3456
#define NFEAT 2304

// ---------------- scratch (static __device__, no allocation) ----------------
__device__ float g_Win[512*NPROJ];
__device__ float g_bvec[NPROJ];
__device__ float g_Wout[NFEAT*512];
__device__ float g_proj[LN*NPROJ];
__device__ float g_cosb[LN*96];
__device__ float g_sinb[LN*96];
__device__ float g_Qf[HN*LN*FQ];
__device__ float g_Kf[HN*LN*FQ];
__device__ float g_Vf[HN*LN*FV];
__device__ float g_attn[HN*LN*LN];
__device__ float g_OV[HN*LN*FV];
__device__ float g_feat[LN*NFEAT];
__device__ float g_part[4*LN*512];

// ---------------- helpers ----------------
// Split v into bf16 hi + bf16 lo (hi = bf16(v), lo = bf16(v - hi)).
// Pack two consecutive-k values into one 32-bit word, even k in LOW half
// (matches mma.m16n8k16 bf16 fragment convention).
__device__ __forceinline__ void split_pair(float ve, float vo,
                                           unsigned& hi, unsigned& lo)
{
    __nv_bfloat16 he = __float2bfloat16(ve), ho = __float2bfloat16(vo);
    float re = ve - __bfloat162float(he);
    float ro = vo - __bfloat162float(ho);
    __nv_bfloat162 th = __halves2bfloat162(he, ho);   // x = low = even k
    __nv_bfloat162 tl = __halves2bfloat162(__float2bfloat16(re),
                                           __float2bfloat16(ro));
    hi = *reinterpret_cast<unsigned*>(&th);
    lo = *reinterpret_cast<unsigned*>(&tl);
}

__device__ __forceinline__ void mma_bf16(float4& d, const unsigned* a,
                                         unsigned b0, unsigned b1) {
    asm volatile(
        "mma.sync.aligned.m16n8k16.row.col.f32.bf16.bf16.f32 "
        "{%0,%1,%2,%3},{%4,%5,%6,%7},{%8,%9},{%0,%1,%2,%3};"
        : "+f"(d.x), "+f"(d.y), "+f"(d.z), "+f"(d.w)
        : "r"(a[0]), "r"(a[1]), "r"(a[2]), "r"(a[3]), "r"(b0), "r"(b1));
}

// ------------- split-BF16 tensor-core GEMM: 128x64 tile, 3-term ------------
// C[M,N] = [C +] A[M,K] @ (TRANSB ? B[N,K]^T : B[K,N]) [+ bias].
// Both operands split a = a_hi + a_lo in bf16 at smem staging, packed as
// k-pairs; k-loop is LDS + 3 bf16 MMAs per fragment pair:
//   acc += al*bh + ah*bl + ah*bh      (al*bl dropped, ~2^-16 relative)
// Effective ~16-bit mantissa per operand -> ~1e-5 relative accuracy.
// Smem: (2*2*8*136 + 2*2*8*72)*4 = 26624 B.
// M%128==0, N%64==0, K%16==0. All pointers float4-aligned.
template<int TRANSB>
__global__ void __launch_bounds__(256)
gemm_bf(const float* __restrict__ A, int lda, long long sA,
        const float* __restrict__ B, int ldb, long long sB,
        float* __restrict__ C, int ldc, long long sC,
        int K, int accum, const float* __restrict__ bias)
{
    __shared__ unsigned Ah16[2][8][136];  // [buf][k2][m] hi pairs
    __shared__ unsigned Al16[2][8][136];  // lo pairs
    __shared__ unsigned Bh16[2][8][72];   // [buf][k2][n]
    __shared__ unsigned Bl16[2][8][72];
    const int bz = blockIdx.z;
    A += (long long)bz * sA;
    B += (long long)bz * sB;
    C += (long long)bz * sC;
    const int row0 = blockIdx.y * 128, col0 = blockIdx.x * 64;
    const int tid = threadIdx.x;
    const int lane = tid & 31, wid = tid >> 5;
    const int g = lane >> 2, tig = lane & 3;
    const int wm = (wid & 3) * 32, wn = (wid >> 2) * 32;

    // A staging: all 256 threads; am row, akq = k-group of 4 floats
    const int am = tid >> 2, akq = tid & 3;
    const float* pA0 = A + (long long)(row0 + am) * lda + akq * 4;
    const float* pA1 = A + (long long)(row0 + am + 64) * lda + akq * 4;

    // B staging pointers
    const float* pB0 = 0; const float* pB1 = 0;
    int bn = 0, bkq = 0, bkk = 0, bnq = 0;
    if (TRANSB) {
        bn = tid >> 2; bkq = tid & 3;
        pB0 = B + (long long)(col0 + bn) * ldb + bkq * 4;
    } else {
        bkk = tid >> 4; bnq = tid & 15;          // valid for tid < 128
        pB0 = B + (long long)(2*bkk)   * ldb + col0 + bnq * 4;
        pB1 = B + (long long)(2*bkk+1) * ldb + col0 + bnq * 4;
    }

    float4 acc[2][4];
#pragma unroll
    for (int mf = 0; mf < 2; mf++)
#pragma unroll
        for (int nf = 0; nf < 4; nf++) acc[mf][nf] = make_float4(0.f,0.f,0.f,0.f);

    float4 ra0 = *(const float4*)pA0;
    float4 ra1 = *(const float4*)pA1;
    float4 rb0 = make_float4(0.f,0.f,0.f,0.f);
    float4 rb1 = make_float4(0.f,0.f,0.f,0.f);
    if (TRANSB) {
        rb0 = *(const float4*)pB0;
    } else if (tid < 128) {
        rb0 = *(const float4*)pB0;
        rb1 = *(const float4*)pB1;
    }

#define STORE_TILE(bf)                                                     \
    do {                                                                   \
        unsigned h0, l0, h1, l1;                                           \
        split_pair(ra0.x, ra0.y, h0, l0);                                  \
        split_pair(ra0.z, ra0.w, h1, l1);                                  \
        Ah16[bf][2*akq  ][am] = h0;  Al16[bf][2*akq  ][am] = l0;           \
        Ah16[bf][2*akq+1][am] = h1;  Al16[bf][2*akq+1][am] = l1;           \
        split_pair(ra1.x, ra1.y, h0, l0);                                  \
        split_pair(ra1.z, ra1.w, h1, l1);                                  \
        Ah16[bf][2*akq  ][am+64] = h0;  Al16[bf][2*akq  ][am+64] = l0;     \
        Ah16[bf][2*akq+1][am+64] = h1;  Al16[bf][2*akq+1][am+64] = l1;     \
        if (TRANSB) {                                                      \
            split_pair(rb0.x, rb0.y, h0, l0);                              \
            split_pair(rb0.z, rb0.w, h1, l1);                              \
            Bh16[bf][2*bkq  ][bn] = h0;  Bl16[bf][2*bkq  ][bn] = l0;       \
            Bh16[bf][2*bkq+1][bn] = h1;  Bl16[bf][2*bkq+1][bn] = l1;       \
        } else if (tid < 128) {                                            \
            unsigned h2, l2, h3, l3;                                       \
            split_pair(rb0.x, rb1.x, h0, l0);                              \
            split_pair(rb0.y, rb1.y, h1, l1);                              \
            split_pair(rb0.z, rb1.z, h2, l2);                              \
            split_pair(rb0.w, rb1.w, h3, l3);                              \
            Bh16[bf][bkk][bnq*4+0] = h0;  Bl16[bf][bkk][bnq*4+0] = l0;     \
            Bh16[bf][bkk][bnq*4+1] = h1;  Bl16[bf][bkk][bnq*4+1] = l1;     \
            Bh16[bf][bkk][bnq*4+2] = h2;  Bl16[bf][bkk][bnq*4+2] = l2;     \
            Bh16[bf][bkk][bnq*4+3] = h3;  Bl16[bf][bkk][bnq*4+3] = l3;     \
        }                                                                  \
    } while (0)

#define COMPUTE_TILE(bf)                                                   \
    do {                                                                   \
        unsigned ah[2][4], al[2][4], bh[4][2], bl[4][2];                   \
        _Pragma("unroll")                                                  \
        for (int mf = 0; mf < 2; mf++) {                                   \
            int m0 = wm + mf * 16;                                         \
            ah[mf][0] = Ah16[bf][tig  ][m0+g  ];                           \
            ah[mf][1] = Ah16[bf][tig  ][m0+g+8];                           \
            ah[mf][2] = Ah16[bf][tig+4][m0+g  ];                           \
            ah[mf][3] = Ah16[bf][tig+4][m0+g+8];                           \
            al[mf][0] = Al16[bf][tig  ][m0+g  ];                           \
            al[mf][1] = Al16[bf][tig  ][m0+g+8];                           \
            al[mf][2] = Al16[bf][tig+4][m0+g  ];                           \
            al[mf][3] = Al16[bf][tig+4][m0+g+8];                           \
        }                                                                  \
        _Pragma("unroll")                                                  \
        for (int nf = 0; nf < 4; nf++) {                                   \
            int n0 = wn + nf * 8;                                          \
            bh[nf][0] = Bh16[bf][tig  ][n0+g];                             \
            bh[nf][1] = Bh16[bf][tig+4][n0+g];                             \
            bl[nf][0] = Bl16[bf][tig  ][n0+g];                             \
            bl[nf][1] = Bl16[bf][tig+4][n0+g];                             \
        }                                                                  \
        _Pragma("unroll")                                                  \
        for (int mf = 0; mf < 2; mf++)                                     \
            _Pragma("unroll")                                              \
            for (int nf = 0; nf < 4; nf++) {                               \
                mma_bf16(acc[mf][nf], al[mf], bh[nf][0], bh[nf][1]);       \
                mma_bf16(acc[mf][nf], ah[mf], bl[nf][0], bl[nf][1]);       \
                mma_bf16(acc[mf][nf], ah[mf], bh[nf][0], bh[nf][1]);       \
            }                                                              \
    } while (0)

    STORE_TILE(0);
    __syncthreads();

    const int T = K >> 4;
    int buf = 0;
#pragma unroll 1
    for (int t = 1; t < T; t++) {
        pA0 += 16; pA1 += 16;
        ra0 = *(const float4*)pA0;
        ra1 = *(const float4*)pA1;
        if (TRANSB) {
            pB0 += 16;
            rb0 = *(const float4*)pB0;
        } else if (tid < 128) {
            pB0 += (long long)16 * ldb;
            pB1 += (long long)16 * ldb;
            rb0 = *(const float4*)pB0;
            rb1 = *(const float4*)pB1;
        }

        COMPUTE_TILE(buf);
        int nb = buf ^ 1;
        STORE_TILE(nb);
        __syncthreads();
        buf = nb;
    }
    COMPUTE_TILE(buf);

    // epilogue: (x,y) -> (row, col..col+1); (z,w) -> (row+8, col..col+1)
#pragma unroll
    for (int mf = 0; mf < 2; mf++) {
#pragma unroll
        for (int nf = 0; nf < 4; nf++) {
            int row = row0 + wm + mf*16 + g;
            int col = col0 + wn + nf*8 + tig*2;
            long long i1 = (long long)row * ldc + col;
            long long i2 = (long long)(row + 8) * ldc + col;
            float4 v = acc[mf][nf];
            if (bias) {
                float b0 = bias[col], b1 = bias[col+1];
                v.x += b0; v.y += b1; v.z += b0; v.w += b1;
            }
            if (accum) {
                float2 o1 = *(float2*)(C + i1);
                float2 o2 = *(float2*)(C + i2);
                v.x += o1.x; v.y += o1.y; v.z += o2.x; v.w += o2.y;
            }
            *(float2*)(C + i1) = make_float2(v.x, v.y);
            *(float2*)(C + i2) = make_float2(v.z, v.w);
        }
    }
#undef STORE_TILE
#undef COMPUTE_TILE
}

// ---------------- weight packing ----------------
__global__ void pack_win(const float* __restrict__ wq, const float* __restrict__ wk,
                         const float* __restrict__ wv, const float* __restrict__ wrq,
                         const float* __restrict__ wqp, const float* __restrict__ wkp,
                         const float* __restrict__ bqp, const float* __restrict__ bkp)
{
    int idx = blockIdx.x * 256 + threadIdx.x;
    if (idx < NPROJ) {
        float bv = 0.f;
        if (idx >= 3168) bv = bkp[idx - 3168];
        else if (idx >= 3072) bv = bqp[idx - 3072];
        g_bvec[idx] = bv;
    }
    if (idx >= 512 * NPROJ) return;
    int k = idx / NPROJ, c = idx % NPROJ;
    float v;
    if (c < 512)       v = wq[k*512 + c];
    else if (c < 1024) v = wk[k*512 + c - 512];
    else if (c < 1536) v = wv[k*512 + c - 1024];
    else if (c < 3072) v = wrq[k*1536 + c - 1536];
    else if (c < 3168) v = wqp[k*96 + c - 3072];
    else               v = wkp[k*288 + c - 3168];
    g_Win[idx] = v;
}

// ---------------- feature construction ----------------
// Qf/Kf layout: [0:192) rope | [192:384) remb cos/sin | [384:396) points
//               | 396 qsq/one | 397 one/ksq | [398:416) zero pad
__global__ void build_features_kernel(const float* __restrict__ trans,
                                      const float* __restrict__ head_w)
{
    int i = blockIdx.x;
    int tid = threadIdx.x;
    __shared__ float s_cos[96], s_sin[96], s_tr[3], s_hw[HN];
    if (tid < 3) s_tr[tid] = trans[i*3 + tid];
    if (tid >= 32 && tid < 32 + HN)
        s_hw[tid-32] = log1pf(expf(head_w[tid-32])) * 0.23570226039551584f;
    __syncthreads();
    if (tid < 96) {
        int c = tid / 32, k = tid % 32;
        float freq = 6.283185307179586f * expf(-(float)k * (logf(100.0f) / 31.0f));
        float sv, cv;
        sincosf(s_tr[c] * freq, &sv, &cv);
        s_cos[tid] = cv; s_sin[tid] = sv;
        g_cosb[i*96 + tid] = cv; g_sinb[i*96 + tid] = sv;
    }
    __syncthreads();

    const float* pr = g_proj + (long long)i * NPROJ;

    for (int idx = tid; idx < HN*192; idx += blockDim.x) {
        int h = idx / 192, d = idx % 192;
        int c = d / 64, f = d % 64;
        int kb = c*32 + (f & 31);
        float cs = s_cos[kb], sn = s_sin[kb];
        int col  = h*64 + f;
        int colp = h*64 + ((f < 32) ? (f + 32) : (f - 32));
        float sgn = (f < 32) ? -1.f : 1.f;
        float qv = pr[col],        q2 = pr[colp];
        float kv = pr[512 + col],  k2 = pr[512 + colp];
        float vv = pr[1024 + col], v2 = pr[1024 + colp];
        long long qo = ((long long)h*LN + i)*FQ + d;
        long long vo = ((long long)h*LN + i)*FV + d;
        g_Qf[qo] = (qv*cs + sgn*q2*sn) * 0.125f;
        g_Kf[qo] = kv*cs + sgn*k2*sn;
        g_Vf[vo] = vv*cs + sgn*v2*sn;
    }
    for (int idx = tid; idx < HN*12; idx += blockDim.x) {
        int h = idx / 12, t = idx % 12;
        int p = t / 3, c = t % 3;
        float qp = pr[3072 + c*32 + h*4  + p] + s_tr[c];
        float kp = pr[3168 + c*96 + h*12 + p] + s_tr[c];
        long long o = ((long long)h*LN + i)*FQ + 384 + t;
        g_Qf[o] = s_hw[h] * qp;
        g_Kf[o] = kp;
    }
    for (int idx = tid; idx < HN*24; idx += blockDim.x) {
        int h = idx / 24, t = idx % 24;
        int p = t / 3, c = t % 3;
        g_Vf[((long long)h*LN + i)*FV + 192 + t] =
            pr[3168 + c*96 + h*12 + 4 + p] + s_tr[c];
    }
    for (int idx = tid; idx < HN*96; idx += blockDim.x) {
        int h = idx / 96, ck = idx % 96;
        int c = ck / 32, k = ck % 32;
        float rqc = pr[1536 + h*192 + c*64 + k];
        float rqs = pr[1536 + h*192 + c*64 + 32 + k];
        float ci = s_cos[ck], si = s_sin[ck];
        const float inv = 0.07216878364870322f; // 1/sqrt(192)
        long long qo = ((long long)h*LN + i)*FQ;
        g_Qf[qo + 192 + ck] = (rqc*ci - rqs*si) * inv;
        g_Qf[qo + 288 + ck] = (rqc*si + rqs*ci) * inv;
        g_Kf[qo + 192 + ck] = ci;
        g_Kf[qo + 288 + ck] = si;
        long long vo = ((long long)h*LN + i)*FV;
        g_Vf[vo + 216 + ck] = ci;
        g_Vf[vo + 312 + ck] = si;
    }
    for (int h = tid; h < HN; h += blockDim.x) {
        float qsq = 0.f, ksq = 0.f;
        for (int p = 0; p < 4; p++)
            for (int c = 0; c < 3; c++) {
                float qv = pr[3072 + c*32 + h*4  + p] + s_tr[c];
                float kv = pr[3168 + c*96 + h*12 + p] + s_tr[c];
                qsq += qv*qv; ksq += kv*kv;
            }
        long long qo = ((long long)h*LN + i)*FQ;
        g_Qf[qo + 396] = -0.5f * s_hw[h] * qsq;
        g_Qf[qo + 397] = -0.5f * s_hw[h];
        g_Kf[qo + 396] = 1.f;
        g_Kf[qo + 397] = ksq;
        for (int t2 = 398; t2 < FQ; t2++) { g_Qf[qo + t2] = 0.f; g_Kf[qo + t2] = 0.f; }
        long long vo = ((long long)h*LN + i)*FV;
        for (int t2 = 408; t2 < FV; t2++) g_Vf[vo + t2] = 0.f;
    }
}

// ---------------- z pair-bias: shuffle-free, smem-tiled --------------------
__global__ void __launch_bounds__(256)
zbias_kernel(const float* __restrict__ z, const float* __restrict__ w_b)
{
    __shared__ float zs[256*36];
    __shared__ float wT[8*128];
    const int tid = threadIdx.x;
    const long long P0 = (long long)blockIdx.x * 256;

    for (int e = tid; e < 1024; e += 256) {
        int h = e >> 7, c = e & 127;
        wT[e] = w_b[c*8 + h];
    }

    float acc[8] = {0.f,0.f,0.f,0.f,0.f,0.f,0.f,0.f};

#pragma unroll
    for (int chunk = 0; chunk < 4; chunk++) {
        const int c0 = chunk * 32;
        __syncthreads();
#pragma unroll
        for (int k = 0; k < 8; k++) {
            int e = k*256 + tid;
            int pp = e >> 3, cq = e & 7;
            float4 v = *(const float4*)(z + (P0 + pp)*128 + c0 + cq*4);
            *(float4*)&zs[pp*36 + cq*4] = v;
        }
        __syncthreads();
#pragma unroll
        for (int s = 0; s < 8; s++) {
            float4 zv = *(const float4*)&zs[tid*36 + s*4];
            int c = c0 + s*4;
#pragma unroll
            for (int h = 0; h < 8; h++) {
                float4 wv = *(const float4*)&wT[h*128 + c];
                acc[h] += zv.x*wv.x + zv.y*wv.y + zv.z*wv.z + zv.w*wv.w;
            }
        }
    }

    const int i = (int)((P0 + tid) >> 9);
    const int j = (int)((P0 + tid) & 511);
#pragma unroll
    for (int h = 0; h < 8; h++)
        g_attn[((long long)h*LN + i)*LN + j] = acc[h];
}

// ---------------- softmax over j ----------------
__global__ void softmax_kernel()
{
    int r = blockIdx.x;
    int tid = threadIdx.x; // 128
    float4* row = (float4*)(g_attn + (long long)r * LN);
    float4 v = row[tid];
    __shared__ float red[128];
    float m = fmaxf(fmaxf(v.x, v.y), fmaxf(v.z, v.w));
    red[tid] = m; __syncthreads();
    for (int s = 64; s > 0; s >>= 1) {
        if (tid < s) red[tid] = fmaxf(red[tid], red[tid+s]);
        __syncthreads();
    }
    float M = red[0]; __syncthreads();
    float e0 = expf(v.x - M), e1 = expf(v.y - M);
    float e2 = expf(v.z - M), e3 = expf(v.w - M);
    red[tid] = e0 + e1 + e2 + e3; __syncthreads();
    for (int s = 64; s > 0; s >>= 1) {
        if (tid < s) red[tid] += red[tid+s];
        __syncthreads();
    }
    float inv = 1.0f / red[0];
    row[tid] = make_float4(e0*inv, e1*inv, e2*inv, e3*inv);
}

// ---------------- epilogue ----------------
__global__ void epilogue_kernel(const float* __restrict__ trans)
{
    int i = blockIdx.x;
    int tid = threadIdx.x;
    __shared__ float s_cos[96], s_sin[96], s_tr[3];
    if (tid < 96) { s_cos[tid] = g_cosb[i*96+tid]; s_sin[tid] = g_sinb[i*96+tid]; }
    if (tid >= 128 && tid < 131) s_tr[tid-128] = trans[i*3 + tid - 128];
    __syncthreads();

    for (int idx = tid; idx < HN*64; idx += blockDim.x) {
        int h = idx / 64, f = idx % 64;
        int kb = f & 31;
        float acc = 0.f;
        long long o = ((long long)h*LN + i)*FV;
#pragma unroll
        for (int c = 0; c < 3; c++) {
            float o1 = g_OV[o + c*64 + f];
            float o2 = g_OV[o + c*64 + ((f < 32) ? (f+32) : (f-32))];
            float cs = s_cos[c*32 + kb], sn = s_sin[c*32 + kb];
            acc += (f < 32) ? (o1*cs + o2*sn) : (o1*cs - o2*sn);
        }
        g_feat[(long long)i*NFEAT + h*64 + f] = acc * (1.0f/3.0f);
    }
    for (int idx = tid; idx < HN*8; idx += blockDim.x) {
        int h = idx / 8, p = idx % 8;
        long long o = ((long long)h*LN + i)*FV + 192 + p*3;
        float ox = g_OV[o+0] - s_tr[0];
        float oy = g_OV[o+1] - s_tr[1];
        float oz = g_OV[o+2] - s_tr[2];
        long long fb = (long long)i*NFEAT + 512;
        g_feat[fb + 0*64 + h*8 + p] = ox;
        g_feat[fb + 1*64 + h*8 + p] = oy;
        g_feat[fb + 2*64 + h*8 + p] = oz;
        g_feat[fb + 192  + h*8 + p] = sqrtf(ox*ox + oy*oy + oz*oz + 1e-6f);
    }
    for (int idx = tid; idx < HN*96; idx += blockDim.x) {
        int h = idx / 96, ck = idx % 96;
        int c = ck / 32, k = ck % 32;
        long long o = ((long long)h*LN + i)*FV;
        float Pc = g_OV[o + 216 + ck];
        float Ps = g_OV[o + 312 + ck];
        float ci = s_cos[ck], si = s_sin[ck];
        long long fb = (long long)i*NFEAT + 768 + h*192 + c*64 + k;
        g_feat[fb]      = ci*Pc + si*Ps;
        g_feat[fb + 32] = ci*Ps - si*Pc;
    }
}

// ---------------- split-K reduce ----------------
__global__ void reduce_out(float* __restrict__ out, const float* __restrict__ b_pt)
{
    int i = blockIdx.x * 256 + threadIdx.x;
    const int S = LN * 512;
    float v = b_pt[i & 511] + g_part[i] + g_part[i + S] + g_part[i + 2*S] + g_part[i + 3*S];
    out[i] = v;
}

// ---------------- host launcher ----------------
static void launch_g(cudaStream_t st,
                     const float* A, int lda, long long sA,
                     const float* B, int ldb, long long sB,
                     float* C, int ldc, long long sC,
                     int M, int N, int K, int batch,
                     int transB, int accum, const float* bias)
{
    dim3 grid(N / 64, M / 128, batch);
    if (transB)
        gemm_bf<1><<<grid, 256, 0, st>>>(A, lda, sA, B, ldb, sB, C, ldc, sC, K, accum, bias);
    else
        gemm_bf<0><<<grid, 256, 0, st>>>(A, lda, sA, B, ldb, sB, C, ldc, sC, K, accum, bias);
}

extern "C" void kernel_launch(void* const* d_in, const int* in_sizes, int n_in,
                              void* d_out, int out_size)
{
    (void)in_sizes; (void)n_in; (void)out_size;
    const float* x       = (const float*)d_in[0];
    const float* z       = (const float*)d_in[1];
    const float* trans   = (const float*)d_in[3];
    const float* w_q     = (const float*)d_in[5];
    const float* w_k     = (const float*)d_in[6];
    const float* w_v     = (const float*)d_in[7];
    const float* w_o     = (const float*)d_in[8];
    const float* w_b     = (const float*)d_in[9];
    const float* w_qpts  = (const float*)d_in[10];
    const float* b_qpts  = (const float*)d_in[11];
    const float* w_kvpts = (const float*)d_in[12];
    const float* b_kvpts = (const float*)d_in[13];
    const float* head_w  = (const float*)d_in[14];
    const float* w_pt    = (const float*)d_in[15];
    const float* b_pt    = (const float*)d_in[16];
    const float* w_rq    = (const float*)d_in[17];
    const float* w_r     = (const float*)d_in[18];
    float* out = (float*)d_out;

    float *p_Win, *p_bvec, *p_Wout, *p_proj, *p_Qf, *p_Kf, *p_Vf, *p_attn, *p_OV, *p_feat, *p_part;
    cudaGetSymbolAddress((void**)&p_Win, g_Win);
    cudaGetSymbolAddress((void**)&p_bvec, g_bvec);
    cudaGetSymbolAddress((void**)&p_Wout, g_Wout);
    cudaGetSymbolAddress((void**)&p_proj, g_proj);
    cudaGetSymbolAddress((void**)&p_Qf, g_Qf);
    cudaGetSymbolAddress((void**)&p_Kf, g_Kf);
    cudaGetSymbolAddress((void**)&p_Vf, g_Vf);
    cudaGetSymbolAddress((void**)&p_attn, g_attn);
    cudaGetSymbolAddress((void**)&p_OV, g_OV);
    cudaGetSymbolAddress((void**)&p_feat, g_feat);
    cudaGetSymbolAddress((void**)&p_part, g_part);

    // One-time side-stream + fork/join events (created on the uncaptured
    // correctness call; reused identically on every call -> deterministic).
    static cudaStream_t s2 = nullptr;
    static cudaEvent_t evFork = nullptr, evJoin = nullptr;
    if (!s2) {
        cudaStreamCreateWithFlags(&s2, cudaStreamNonBlocking);
        cudaEventCreateWithFlags(&evFork, cudaEventDisableTiming);
        cudaEventCreateWithFlags(&evJoin, cudaEventDisableTiming);
    }

    // ---- fork: s2 runs zbias + Wout staging, concurrent with main chain ----
    cudaEventRecord(evFork, 0);
    cudaStreamWaitEvent(s2, evFork, 0);
    zbias_kernel<<<LN*LN/256, 256, 0, s2>>>(z, w_b);
    cudaMemcpyAsync(p_Wout,            w_o,  512*512*sizeof(float),  cudaMemcpyDeviceToDevice, s2);
    cudaMemcpyAsync(p_Wout + 512*512,  w_pt, 256*512*sizeof(float),  cudaMemcpyDeviceToDevice, s2);
    cudaMemcpyAsync(p_Wout + 768*512,  w_r,  1536*512*sizeof(float), cudaMemcpyDeviceToDevice, s2);
    cudaEventRecord(evJoin, s2);

    // ---- main chain (default stream) ----
    // 0) pack fused projection weights
    pack_win<<<(512*NPROJ + 255)/256, 256>>>(w_q, w_k, w_v, w_rq, w_qpts, w_kvpts,
                                             b_qpts, b_kvpts);

    // 1) input projections (split-bf16, fused bias), one launch
    launch_g(0, x, 512, 0, p_Win, NPROJ, 0, p_proj, NPROJ, 0,
             512, NPROJ, 512, 1, 0, 0, p_bvec);

    // 2) feature construction
    build_features_kernel<<<512, 256>>>(trans, head_w);

    // ---- join: logits accumulates onto z bias; Wout staged for step 8 ----
    cudaStreamWaitEvent(0, evJoin, 0);

    // 4) logits: Qf @ Kf^T; K=400 covers all non-zero dims (398)
    launch_g(0, p_Qf, FQ, (long long)LN*FQ, p_Kf, FQ, (long long)LN*FQ,
             p_attn, LN, (long long)LN*LN, 512, 512, 400, HN, 1, 1, 0);

    // 5) softmax
    softmax_kernel<<<HN*LN, 128>>>();

    // 6) value side
    launch_g(0, p_attn, LN, (long long)LN*LN, p_Vf, FV, (long long)LN*FV,
             p_OV, FV, (long long)LN*FV, 512, FV, 512, HN, 0, 0, 0);

    // 7) epilogue features
    epilogue_kernel<<<512, 256>>>(trans);

    // 8) output projection (split-K x4) + reduce
    launch_g(0, p_feat, NFEAT, 576, p_Wout, 512, (long long)576*512,
             p_part, 512, (long long)LN*512, 512, 512, 576, 4, 0, 0, 0);
    reduce_out<<<LN*512/256, 256>>>(out, b_pt);
}

// round 15
// speedup vs baseline: 1.4841x; 1.0120x over previous
#include <cuda_runtime.h>
#include <cuda_bf16.h>
#include <math.h>

#define HN 8
#define LN 512
#define FQ 416
#define FV 448
#define NPROJ 3456
#define NFEAT 2304

// ---------------- scratch (static __device__, no allocation) ----------------
__device__ float g_Wout[NFEAT*512];
__device__ float g_proj[LN*NPROJ];
__device__ float g_cosb[LN*96];
__device__ float g_sinb[LN*96];
__device__ float g_Qf[HN*LN*FQ];
__device__ float g_Kf[HN*LN*FQ];
__device__ float g_Vf[HN*LN*FV];
__device__ float g_attn[HN*LN*LN];
__device__ float g_OV[HN*LN*FV];
__device__ float g_feat[LN*NFEAT];
__device__ float g_part[4*LN*512];

// ---------------- helpers ----------------
// Split v into bf16 hi + bf16 lo; pack two consecutive-k values per word
// (even k in LOW half, matching mma.m16n8k16 bf16 fragment convention).
__device__ __forceinline__ void split_pair(float ve, float vo,
                                           unsigned& hi, unsigned& lo)
{
    __nv_bfloat16 he = __float2bfloat16(ve), ho = __float2bfloat16(vo);
    float re = ve - __bfloat162float(he);
    float ro = vo - __bfloat162float(ho);
    __nv_bfloat162 th = __halves2bfloat162(he, ho);
    __nv_bfloat162 tl = __halves2bfloat162(__float2bfloat16(re),
                                           __float2bfloat16(ro));
    hi = *reinterpret_cast<unsigned*>(&th);
    lo = *reinterpret_cast<unsigned*>(&tl);
}

__device__ __forceinline__ void mma_bf16(float4& d, const unsigned* a,
                                         unsigned b0, unsigned b1) {
    asm volatile(
        "mma.sync.aligned.m16n8k16.row.col.f32.bf16.bf16.f32 "
        "{%0,%1,%2,%3},{%4,%5,%6,%7},{%8,%9},{%0,%1,%2,%3};"
        : "+f"(d.x), "+f"(d.y), "+f"(d.z), "+f"(d.w)
        : "r"(a[0]), "r"(a[1]), "r"(a[2]), "r"(a[3]), "r"(b0), "r"(b1));
}

// ------------- split-BF16 tensor-core GEMM: 128x64 tile, 3-term ------------
// C[M,N] = [C +] A[M,K] @ (TRANSB ? B[N,K]^T : B[K,N]) [+ bias].
// GATHER=1 (proj only, TRANSB=0): B columns gathered directly from the six
// weight arrays (per-thread segment resolved once); bias from bqp/bkp in
// the epilogue. Removes the pack_win pass entirely.
// acc += al*bh + ah*bl + ah*bh  (al*bl dropped, ~2^-16 relative).
template<int TRANSB, int GATHER>
__global__ void __launch_bounds__(256)
gemm_bf(const float* __restrict__ A, int lda, long long sA,
        const float* __restrict__ B, int ldb, long long sB,
        float* __restrict__ C, int ldc, long long sC,
        int K, int accum, const float* __restrict__ bias,
        const float* __restrict__ wq, const float* __restrict__ wk,
        const float* __restrict__ wv, const float* __restrict__ wrq,
        const float* __restrict__ wqp, const float* __restrict__ wkp,
        const float* __restrict__ bqp, const float* __restrict__ bkp)
{
    __shared__ unsigned Ah16[2][8][136];
    __shared__ unsigned Al16[2][8][136];
    __shared__ unsigned Bh16[2][8][72];
    __shared__ unsigned Bl16[2][8][72];
    const int bz = blockIdx.z;
    A += (long long)bz * sA;
    if (!GATHER) B += (long long)bz * sB;
    C += (long long)bz * sC;
    const int row0 = blockIdx.y * 128, col0 = blockIdx.x * 64;
    const int tid = threadIdx.x;
    const int lane = tid & 31, wid = tid >> 5;
    const int g = lane >> 2, tig = lane & 3;
    const int wm = (wid & 3) * 32, wn = (wid >> 2) * 32;

    const int am = tid >> 2, akq = tid & 3;
    const float* pA0 = A + (long long)(row0 + am) * lda + akq * 4;
    const float* pA1 = A + (long long)(row0 + am + 64) * lda + akq * 4;

    const float* pB0 = 0; const float* pB1 = 0;
    long long bstep = 0;
    int bn = 0, bkq = 0, bkk = 0, bnq = 0;
    if (TRANSB) {
        bn = tid >> 2; bkq = tid & 3;
        pB0 = B + (long long)(col0 + bn) * ldb + bkq * 4;
    } else {
        bkk = tid >> 4; bnq = tid & 15;          // valid for tid < 128
        if (GATHER) {
            int cl = col0 + bnq * 4;
            const float* base; int ldseg, off;
            if (cl < 512)       { base = wq;  ldseg = 512;  off = cl; }
            else if (cl < 1024) { base = wk;  ldseg = 512;  off = cl - 512; }
            else if (cl < 1536) { base = wv;  ldseg = 512;  off = cl - 1024; }
            else if (cl < 3072) { base = wrq; ldseg = 1536; off = cl - 1536; }
            else if (cl < 3168) { base = wqp; ldseg = 96;   off = cl - 3072; }
            else                { base = wkp; ldseg = 288;  off = cl - 3168; }
            pB0 = base + (long long)(2*bkk)   * ldseg + off;
            pB1 = base + (long long)(2*bkk+1) * ldseg + off;
            bstep = (long long)16 * ldseg;
        } else {
            pB0 = B + (long long)(2*bkk)   * ldb + col0 + bnq * 4;
            pB1 = B + (long long)(2*bkk+1) * ldb + col0 + bnq * 4;
            bstep = (long long)16 * ldb;
        }
    }

    float4 acc[2][4];
#pragma unroll
    for (int mf = 0; mf < 2; mf++)
#pragma unroll
        for (int nf = 0; nf < 4; nf++) acc[mf][nf] = make_float4(0.f,0.f,0.f,0.f);

    float4 ra0 = *(const float4*)pA0;
    float4 ra1 = *(const float4*)pA1;
    float4 rb0 = make_float4(0.f,0.f,0.f,0.f);
    float4 rb1 = make_float4(0.f,0.f,0.f,0.f);
    if (TRANSB) {
        rb0 = *(const float4*)pB0;
    } else if (tid < 128) {
        rb0 = *(const float4*)pB0;
        rb1 = *(const float4*)pB1;
    }

#define STORE_TILE(bf)                                                     \
    do {                                                                   \
        unsigned h0, l0, h1, l1;                                           \
        split_pair(ra0.x, ra0.y, h0, l0);                                  \
        split_pair(ra0.z, ra0.w, h1, l1);                                  \
        Ah16[bf][2*akq  ][am] = h0;  Al16[bf][2*akq  ][am] = l0;           \
        Ah16[bf][2*akq+1][am] = h1;  Al16[bf][2*akq+1][am] = l1;           \
        split_pair(ra1.x, ra1.y, h0, l0);                                  \
        split_pair(ra1.z, ra1.w, h1, l1);                                  \
        Ah16[bf][2*akq  ][am+64] = h0;  Al16[bf][2*akq  ][am+64] = l0;     \
        Ah16[bf][2*akq+1][am+64] = h1;  Al16[bf][2*akq+1][am+64] = l1;     \
        if (TRANSB) {                                                      \
            split_pair(rb0.x, rb0.y, h0, l0);                              \
            split_pair(rb0.z, rb0.w, h1, l1);                              \
            Bh16[bf][2*bkq  ][bn] = h0;  Bl16[bf][2*bkq  ][bn] = l0;       \
            Bh16[bf][2*bkq+1][bn] = h1;  Bl16[bf][2*bkq+1][bn] = l1;       \
        } else if (tid < 128) {                                            \
            unsigned h2, l2, h3, l3;                                       \
            split_pair(rb0.x, rb1.x, h0, l0);                              \
            split_pair(rb0.y, rb1.y, h1, l1);                              \
            split_pair(rb0.z, rb1.z, h2, l2);                              \
            split_pair(rb0.w, rb1.w, h3, l3);                              \
            Bh16[bf][bkk][bnq*4+0] = h0;  Bl16[bf][bkk][bnq*4+0] = l0;     \
            Bh16[bf][bkk][bnq*4+1] = h1;  Bl16[bf][bkk][bnq*4+1] = l1;     \
            Bh16[bf][bkk][bnq*4+2] = h2;  Bl16[bf][bkk][bnq*4+2] = l2;     \
            Bh16[bf][bkk][bnq*4+3] = h3;  Bl16[bf][bkk][bnq*4+3] = l3;     \
        }                                                                  \
    } while (0)

#define COMPUTE_TILE(bf)                                                   \
    do {                                                                   \
        unsigned ah[2][4], al[2][4], bh[4][2], bl[4][2];                   \
        _Pragma("unroll")                                                  \
        for (int mf = 0; mf < 2; mf++) {                                   \
            int m0 = wm + mf * 16;                                         \
            ah[mf][0] = Ah16[bf][tig  ][m0+g  ];                           \
            ah[mf][1] = Ah16[bf][tig  ][m0+g+8];                           \
            ah[mf][2] = Ah16[bf][tig+4][m0+g  ];                           \
            ah[mf][3] = Ah16[bf][tig+4][m0+g+8];                           \
            al[mf][0] = Al16[bf][tig  ][m0+g  ];                           \
            al[mf][1] = Al16[bf][tig  ][m0+g+8];                           \
            al[mf][2] = Al16[bf][tig+4][m0+g  ];                           \
            al[mf][3] = Al16[bf][tig+4][m0+g+8];                           \
        }                                                                  \
        _Pragma("unroll")                                                  \
        for (int nf = 0; nf < 4; nf++) {                                   \
            int n0 = wn + nf * 8;                                          \
            bh[nf][0] = Bh16[bf][tig  ][n0+g];                             \
            bh[nf][1] = Bh16[bf][tig+4][n0+g];                             \
            bl[nf][0] = Bl16[bf][tig  ][n0+g];                             \
            bl[nf][1] = Bl16[bf][tig+4][n0+g];                             \
        }                                                                  \
        _Pragma("unroll")                                                  \
        for (int mf = 0; mf < 2; mf++)                                     \
            _Pragma("unroll")                                              \
            for (int nf = 0; nf < 4; nf++) {                               \
                mma_bf16(acc[mf][nf], al[mf], bh[nf][0], bh[nf][1]);       \
                mma_bf16(acc[mf][nf], ah[mf], bl[nf][0], bl[nf][1]);       \
                mma_bf16(acc[mf][nf], ah[mf], bh[nf][0], bh[nf][1]);       \
            }                                                              \
    } while (0)

    STORE_TILE(0);
    __syncthreads();

    const int T = K >> 4;
    int buf = 0;
#pragma unroll 1
    for (int t = 1; t < T; t++) {
        pA0 += 16; pA1 += 16;
        ra0 = *(const float4*)pA0;
        ra1 = *(const float4*)pA1;
        if (TRANSB) {
            pB0 += 16;
            rb0 = *(const float4*)pB0;
        } else if (tid < 128) {
            pB0 += bstep;
            pB1 += bstep;
            rb0 = *(const float4*)pB0;
            rb1 = *(const float4*)pB1;
        }

        COMPUTE_TILE(buf);
        int nb = buf ^ 1;
        STORE_TILE(nb);
        __syncthreads();
        buf = nb;
    }
    COMPUTE_TILE(buf);

    // epilogue
#pragma unroll
    for (int mf = 0; mf < 2; mf++) {
#pragma unroll
        for (int nf = 0; nf < 4; nf++) {
            int row = row0 + wm + mf*16 + g;
            int col = col0 + wn + nf*8 + tig*2;
            long long i1 = (long long)row * ldc + col;
            long long i2 = (long long)(row + 8) * ldc + col;
            float4 v = acc[mf][nf];
            if (GATHER) {
                float b0 = 0.f, b1 = 0.f;
                if (col >= 3168)      b0 = bkp[col - 3168];
                else if (col >= 3072) b0 = bqp[col - 3072];
                int c1 = col + 1;
                if (c1 >= 3168)       b1 = bkp[c1 - 3168];
                else if (c1 >= 3072)  b1 = bqp[c1 - 3072];
                v.x += b0; v.y += b1; v.z += b0; v.w += b1;
            } else if (bias) {
                float b0 = bias[col], b1 = bias[col+1];
                v.x += b0; v.y += b1; v.z += b0; v.w += b1;
            }
            if (accum) {
                float2 o1 = *(float2*)(C + i1);
                float2 o2 = *(float2*)(C + i2);
                v.x += o1.x; v.y += o1.y; v.z += o2.x; v.w += o2.y;
            }
            *(float2*)(C + i1) = make_float2(v.x, v.y);
            *(float2*)(C + i2) = make_float2(v.z, v.w);
        }
    }
#undef STORE_TILE
#undef COMPUTE_TILE
}

// ---------------- feature construction ----------------
__global__ void build_features_kernel(const float* __restrict__ trans,
                                      const float* __restrict__ head_w)
{
    int i = blockIdx.x;
    int tid = threadIdx.x;
    __shared__ float s_cos[96], s_sin[96], s_tr[3], s_hw[HN];
    if (tid < 3) s_tr[tid] = trans[i*3 + tid];
    if (tid >= 32 && tid < 32 + HN)
        s_hw[tid-32] = log1pf(expf(head_w[tid-32])) * 0.23570226039551584f;
    __syncthreads();
    if (tid < 96) {
        int c = tid / 32, k = tid % 32;
        float freq = 6.283185307179586f * expf(-(float)k * (logf(100.0f) / 31.0f));
        float sv, cv;
        sincosf(s_tr[c] * freq, &sv, &cv);
        s_cos[tid] = cv; s_sin[tid] = sv;
        g_cosb[i*96 + tid] = cv; g_sinb[i*96 + tid] = sv;
    }
    __syncthreads();

    const float* pr = g_proj + (long long)i * NPROJ;

    for (int idx = tid; idx < HN*192; idx += blockDim.x) {
        int h = idx / 192, d = idx % 192;
        int c = d / 64, f = d % 64;
        int kb = c*32 + (f & 31);
        float cs = s_cos[kb], sn = s_sin[kb];
        int col  = h*64 + f;
        int colp = h*64 + ((f < 32) ? (f + 32) : (f - 32));
        float sgn = (f < 32) ? -1.f : 1.f;
        float qv = pr[col],        q2 = pr[colp];
        float kv = pr[512 + col],  k2 = pr[512 + colp];
        float vv = pr[1024 + col], v2 = pr[1024 + colp];
        long long qo = ((long long)h*LN + i)*FQ + d;
        long long vo = ((long long)h*LN + i)*FV + d;
        g_Qf[qo] = (qv*cs + sgn*q2*sn) * 0.125f;
        g_Kf[qo] = kv*cs + sgn*k2*sn;
        g_Vf[vo] = vv*cs + sgn*v2*sn;
    }
    for (int idx = tid; idx < HN*12; idx += blockDim.x) {
        int h = idx / 12, t = idx % 12;
        int p = t / 3, c = t % 3;
        float qp = pr[3072 + c*32 + h*4  + p] + s_tr[c];
        float kp = pr[3168 + c*96 + h*12 + p] + s_tr[c];
        long long o = ((long long)h*LN + i)*FQ + 384 + t;
        g_Qf[o] = s_hw[h] * qp;
        g_Kf[o] = kp;
    }
    for (int idx = tid; idx < HN*24; idx += blockDim.x) {
        int h = idx / 24, t = idx % 24;
        int p = t / 3, c = t % 3;
        g_Vf[((long long)h*LN + i)*FV + 192 + t] =
            pr[3168 + c*96 + h*12 + 4 + p] + s_tr[c];
    }
    for (int idx = tid; idx < HN*96; idx += blockDim.x) {
        int h = idx / 96, ck = idx % 96;
        int c = ck / 32, k = ck % 32;
        float rqc = pr[1536 + h*192 + c*64 + k];
        float rqs = pr[1536 + h*192 + c*64 + 32 + k];
        float ci = s_cos[ck], si = s_sin[ck];
        const float inv = 0.07216878364870322f; // 1/sqrt(192)
        long long qo = ((long long)h*LN + i)*FQ;
        g_Qf[qo + 192 + ck] = (rqc*ci - rqs*si) * inv;
        g_Qf[qo + 288 + ck] = (rqc*si + rqs*ci) * inv;
        g_Kf[qo + 192 + ck] = ci;
        g_Kf[qo + 288 + ck] = si;
        long long vo = ((long long)h*LN + i)*FV;
        g_Vf[vo + 216 + ck] = ci;
        g_Vf[vo + 312 + ck] = si;
    }
    for (int h = tid; h < HN; h += blockDim.x) {
        float qsq = 0.f, ksq = 0.f;
        for (int p = 0; p < 4; p++)
            for (int c = 0; c < 3; c++) {
                float qv = pr[3072 + c*32 + h*4  + p] + s_tr[c];
                float kv = pr[3168 + c*96 + h*12 + p] + s_tr[c];
                qsq += qv*qv; ksq += kv*kv;
            }
        long long qo = ((long long)h*LN + i)*FQ;
        g_Qf[qo + 396] = -0.5f * s_hw[h] * qsq;
        g_Qf[qo + 397] = -0.5f * s_hw[h];
        g_Kf[qo + 396] = 1.f;
        g_Kf[qo + 397] = ksq;
        for (int t2 = 398; t2 < FQ; t2++) { g_Qf[qo + t2] = 0.f; g_Kf[qo + t2] = 0.f; }
        long long vo = ((long long)h*LN + i)*FV;
        for (int t2 = 408; t2 < FV; t2++) g_Vf[vo + t2] = 0.f;
    }
}

// ---------------- z pair-bias: shuffle-free, smem-tiled --------------------
__global__ void __launch_bounds__(256)
zbias_kernel(const float* __restrict__ z, const float* __restrict__ w_b)
{
    __shared__ float zs[256*36];
    __shared__ float wT[8*128];
    const int tid = threadIdx.x;
    const long long P0 = (long long)blockIdx.x * 256;

    for (int e = tid; e < 1024; e += 256) {
        int h = e >> 7, c = e & 127;
        wT[e] = w_b[c*8 + h];
    }

    float acc[8] = {0.f,0.f,0.f,0.f,0.f,0.f,0.f,0.f};

#pragma unroll
    for (int chunk = 0; chunk < 4; chunk++) {
        const int c0 = chunk * 32;
        __syncthreads();
#pragma unroll
        for (int k = 0; k < 8; k++) {
            int e = k*256 + tid;
            int pp = e >> 3, cq = e & 7;
            float4 v = *(const float4*)(z + (P0 + pp)*128 + c0 + cq*4);
            *(float4*)&zs[pp*36 + cq*4] = v;
        }
        __syncthreads();
#pragma unroll
        for (int s = 0; s < 8; s++) {
            float4 zv = *(const float4*)&zs[tid*36 + s*4];
            int c = c0 + s*4;
#pragma unroll
            for (int h = 0; h < 8; h++) {
                float4 wv = *(const float4*)&wT[h*128 + c];
                acc[h] += zv.x*wv.x + zv.y*wv.y + zv.z*wv.z + zv.w*wv.w;
            }
        }
    }

    const int i = (int)((P0 + tid) >> 9);
    const int j = (int)((P0 + tid) & 511);
#pragma unroll
    for (int h = 0; h < 8; h++)
        g_attn[((long long)h*LN + i)*LN + j] = acc[h];
}

// ---------------- softmax over j ----------------
__global__ void softmax_kernel()
{
    int r = blockIdx.x;
    int tid = threadIdx.x; // 128
    float4* row = (float4*)(g_attn + (long long)r * LN);
    float4 v = row[tid];
    __shared__ float red[128];
    float m = fmaxf(fmaxf(v.x, v.y), fmaxf(v.z, v.w));
    red[tid] = m; __syncthreads();
    for (int s = 64; s > 0; s >>= 1) {
        if (tid < s) red[tid] = fmaxf(red[tid], red[tid+s]);
        __syncthreads();
    }
    float M = red[0]; __syncthreads();
    float e0 = expf(v.x - M), e1 = expf(v.y - M);
    float e2 = expf(v.z - M), e3 = expf(v.w - M);
    red[tid] = e0 + e1 + e2 + e3; __syncthreads();
    for (int s = 64; s > 0; s >>= 1) {
        if (tid < s) red[tid] += red[tid+s];
        __syncthreads();
    }
    float inv = 1.0f / red[0];
    row[tid] = make_float4(e0*inv, e1*inv, e2*inv, e3*inv);
}

// ---------------- epilogue ----------------
__global__ void epilogue_kernel(const float* __restrict__ trans)
{
    int i = blockIdx.x;
    int tid = threadIdx.x;
    __shared__ float s_cos[96], s_sin[96], s_tr[3];
    if (tid < 96) { s_cos[tid] = g_cosb[i*96+tid]; s_sin[tid] = g_sinb[i*96+tid]; }
    if (tid >= 128 && tid < 131) s_tr[tid-128] = trans[i*3 + tid - 128];
    __syncthreads();

    for (int idx = tid; idx < HN*64; idx += blockDim.x) {
        int h = idx / 64, f = idx % 64;
        int kb = f & 31;
        float acc = 0.f;
        long long o = ((long long)h*LN + i)*FV;
#pragma unroll
        for (int c = 0; c < 3; c++) {
            float o1 = g_OV[o + c*64 + f];
            float o2 = g_OV[o + c*64 + ((f < 32) ? (f+32) : (f-32))];
            float cs = s_cos[c*32 + kb], sn = s_sin[c*32 + kb];
            acc += (f < 32) ? (o1*cs + o2*sn) : (o1*cs - o2*sn);
        }
        g_feat[(long long)i*NFEAT + h*64 + f] = acc * (1.0f/3.0f);
    }
    for (int idx = tid; idx < HN*8; idx += blockDim.x) {
        int h = idx / 8, p = idx % 8;
        long long o = ((long long)h*LN + i)*FV + 192 + p*3;
        float ox = g_OV[o+0] - s_tr[0];
        float oy = g_OV[o+1] - s_tr[1];
        float oz = g_OV[o+2] - s_tr[2];
        long long fb = (long long)i*NFEAT + 512;
        g_feat[fb + 0*64 + h*8 + p] = ox;
        g_feat[fb + 1*64 + h*8 + p] = oy;
        g_feat[fb + 2*64 + h*8 + p] = oz;
        g_feat[fb + 192  + h*8 + p] = sqrtf(ox*ox + oy*oy + oz*oz + 1e-6f);
    }
    for (int idx = tid; idx < HN*96; idx += blockDim.x) {
        int h = idx / 96, ck = idx % 96;
        int c = ck / 32, k = ck % 32;
        long long o = ((long long)h*LN + i)*FV;
        float Pc = g_OV[o + 216 + ck];
        float Ps = g_OV[o + 312 + ck];
        float ci = s_cos[ck], si = s_sin[ck];
        long long fb = (long long)i*NFEAT + 768 + h*192 + c*64 + k;
        g_feat[fb]      = ci*Pc + si*Ps;
        g_feat[fb + 32] = ci*Ps - si*Pc;
    }
}

// ---------------- split-K reduce ----------------
__global__ void reduce_out(float* __restrict__ out, const float* __restrict__ b_pt)
{
    int i = blockIdx.x * 256 + threadIdx.x;
    const int S = LN * 512;
    float v = b_pt[i & 511] + g_part[i] + g_part[i + S] + g_part[i + 2*S] + g_part[i + 3*S];
    out[i] = v;
}

// ---------------- host launchers ----------------
static void launch_g(cudaStream_t st,
                     const float* A, int lda, long long sA,
                     const float* B, int ldb, long long sB,
                     float* C, int ldc, long long sC,
                     int M, int N, int K, int batch,
                     int transB, int accum)
{
    dim3 grid(N / 64, M / 128, batch);
    if (transB)
        gemm_bf<1,0><<<grid, 256, 0, st>>>(A, lda, sA, B, ldb, sB, C, ldc, sC,
                                           K, accum, 0, 0,0,0,0,0,0,0,0);
    else
        gemm_bf<0,0><<<grid, 256, 0, st>>>(A, lda, sA, B, ldb, sB, C, ldc, sC,
                                           K, accum, 0, 0,0,0,0,0,0,0,0);
}

extern "C" void kernel_launch(void* const* d_in, const int* in_sizes, int n_in,
                              void* d_out, int out_size)
{
    (void)in_sizes; (void)n_in; (void)out_size;
    const float* x       = (const float*)d_in[0];
    const float* z       = (const float*)d_in[1];
    const float* trans   = (const float*)d_in[3];
    const float* w_q     = (const float*)d_in[5];
    const float* w_k     = (const float*)d_in[6];
    const float* w_v     = (const float*)d_in[7];
    const float* w_o     = (const float*)d_in[8];
    const float* w_b     = (const float*)d_in[9];
    const float* w_qpts  = (const float*)d_in[10];
    const float* b_qpts  = (const float*)d_in[11];
    const float* w_kvpts = (const float*)d_in[12];
    const float* b_kvpts = (const float*)d_in[13];
    const float* head_w  = (const float*)d_in[14];
    const float* w_pt    = (const float*)d_in[15];
    const float* b_pt    = (const float*)d_in[16];
    const float* w_rq    = (const float*)d_in[17];
    const float* w_r     = (const float*)d_in[18];
    float* out = (float*)d_out;

    float *p_Wout, *p_proj, *p_Qf, *p_Kf, *p_Vf, *p_attn, *p_OV, *p_feat, *p_part;
    cudaGetSymbolAddress((void**)&p_Wout, g_Wout);
    cudaGetSymbolAddress((void**)&p_proj, g_proj);
    cudaGetSymbolAddress((void**)&p_Qf, g_Qf);
    cudaGetSymbolAddress((void**)&p_Kf, g_Kf);
    cudaGetSymbolAddress((void**)&p_Vf, g_Vf);
    cudaGetSymbolAddress((void**)&p_attn, g_attn);
    cudaGetSymbolAddress((void**)&p_OV, g_OV);
    cudaGetSymbolAddress((void**)&p_feat, g_feat);
    cudaGetSymbolAddress((void**)&p_part, g_part);

    // One-time side-stream + fork/join events (created on the uncaptured
    // correctness call; reused identically on every call -> deterministic).
    static cudaStream_t s2 = nullptr;
    static cudaEvent_t evFork = nullptr, evJoin = nullptr;
    if (!s2) {
        cudaStreamCreateWithFlags(&s2, cudaStreamNonBlocking);
        cudaEventCreateWithFlags(&evFork, cudaEventDisableTiming);
        cudaEventCreateWithFlags(&evJoin, cudaEventDisableTiming);
    }

    // ---- fork: s2 runs zbias + Wout staging, concurrent with main chain ----
    cudaEventRecord(evFork, 0);
    cudaStreamWaitEvent(s2, evFork, 0);
    zbias_kernel<<<LN*LN/256, 256, 0, s2>>>(z, w_b);
    cudaMemcpyAsync(p_Wout,            w_o,  512*512*sizeof(float),  cudaMemcpyDeviceToDevice, s2);
    cudaMemcpyAsync(p_Wout + 512*512,  w_pt, 256*512*sizeof(float),  cudaMemcpyDeviceToDevice, s2);
    cudaMemcpyAsync(p_Wout + 768*512,  w_r,  1536*512*sizeof(float), cudaMemcpyDeviceToDevice, s2);
    cudaEventRecord(evJoin, s2);

    // ---- main chain (default stream) ----
    // 1) input projections: B gathered directly from weight arrays (no pack)
    {
        dim3 grid(NPROJ / 64, 512 / 128, 1);
        gemm_bf<0,1><<<grid, 256>>>(x, 512, 0, (const float*)0, 0, 0,
                                    p_proj, NPROJ, 0, 512, 0, 0,
                                    w_q, w_k, w_v, w_rq, w_qpts, w_kvpts,
                                    b_qpts, b_kvpts);
    }

    // 2) feature construction
    build_features_kernel<<<512, 256>>>(trans, head_w);

    // ---- join: logits accumulates onto z bias; Wout staged for step 8 ----
    cudaStreamWaitEvent(0, evJoin, 0);

    // 4) logits: Qf @ Kf^T; K=400 covers all non-zero dims (398)
    launch_g(0, p_Qf, FQ, (long long)LN*FQ, p_Kf, FQ, (long long)LN*FQ,
             p_attn, LN, (long long)LN*LN, 512, 512, 400, HN, 1, 1);

    // 5) softmax
    softmax_kernel<<<HN*LN, 128>>>();

    // 6) value side
    launch_g(0, p_attn, LN, (long long)LN*LN, p_Vf, FV, (long long)LN*FV,
             p_OV, FV, (long long)LN*FV, 512, FV, 512, HN, 0, 0);

    // 7) epilogue features
    epilogue_kernel<<<512, 256>>>(trans);

    // 8) output projection (split-K x4) + reduce
    launch_g(0, p_feat, NFEAT, 576, p_Wout, 512, (long long)576*512,
             p_part, 512, (long long)LN*512, 512, 512, 576, 4, 0, 0);
    reduce_out<<<LN*512/256, 256>>>(out, b_pt);
}